// round 7
// baseline (speedup 1.0000x reference)
#include <cuda_runtime.h>
#include <cuda_bf16.h>
#include <math.h>
#include <stdint.h>

static constexpr int N_ = 50000;
static constexpr int E_ = 200000;

// ---------------- scratch ----------------
__device__ __nv_bfloat16 g_X3   [(size_t)N_ * 768];   // split [hi|lo|hi] of [nf|mem]
__device__ float         g_h    [(size_t)N_ * 256];
__device__ __nv_bfloat16 g_h3   [(size_t)N_ * 768];   // split of h
__device__ float         g_hkvqp[(size_t)N_ * 1152];  // [K'|V'|Q'|P(320)|pad] (biases folded)
__device__ float         g_agg  [(size_t)N_ * 256];
__device__ float         g_agg2 [(size_t)N_ * 256];
__device__ float         g_aggm [(size_t)N_ * 80];
__device__ __nv_bfloat16 g_aggm3[(size_t)N_ * 256];   // split of aggm (K0=80, pad 256)
__device__ float         g_nrm  [N_];
__device__ float         g_Wall [2 * 1152 * 256];     // fp32 [Wk;Wv;Wq;Wfused;0]
__device__ __nv_bfloat16 g_Wall3[2 * 1152 * 768];
__device__ float         g_bias1152[2 * 1152];        // [bk|bv|bq_eff|cb|0]
__device__ __nv_bfloat16 g_Win3 [256 * 768];
__device__ float         g_Wev  [2 * 256 * 80];
__device__ __nv_bfloat16 g_Wev3 [2 * 256 * 256];
__device__ __nv_bfloat16 g_Wout3[64 * 768];
__device__ float         g_b    [2 * 768];            // [bk|bv|bq_eff]

// ---------------- ptx helpers (family-safe, sm_80 baseline) ----------------
__device__ __forceinline__ uint32_t smem_u32(const void* p) {
    uint32_t a;
    asm("{ .reg .u64 t; cvta.to.shared.u64 t, %1; cvt.u32.u64 %0, t; }" : "=r"(a) : "l"(p));
    return a;
}
__device__ __forceinline__ void cp16(uint32_t dst, const void* src, int pred) {
    asm volatile(
        "{\n\t.reg .pred p;\n\t"
        "setp.ne.u32 p, %2, 0;\n\t"
        "@p cp.async.ca.shared.global [%0], [%1], 16;\n\t"
        "@!p cp.async.ca.shared.global [%0], [%1], 16, 0;\n\t}"
        :: "r"(dst), "l"(src), "r"(pred) : "memory");
}
__device__ __forceinline__ void cp_commit() {
    asm volatile("cp.async.commit_group;" ::: "memory");
}
__device__ __forceinline__ void ldm4(uint32_t* r, uint32_t addr) {
    asm volatile("ldmatrix.sync.aligned.m8n8.x4.shared.b16 {%0,%1,%2,%3}, [%4];"
                 : "=r"(r[0]), "=r"(r[1]), "=r"(r[2]), "=r"(r[3]) : "r"(addr));
}
__device__ __forceinline__ void ldm2(uint32_t* r, uint32_t addr) {
    asm volatile("ldmatrix.sync.aligned.m8n8.x2.shared.b16 {%0,%1}, [%2];"
                 : "=r"(r[0]), "=r"(r[1]) : "r"(addr));
}
__device__ __forceinline__ void mma16816(float* c, const uint32_t* a, const uint32_t* b) {
    asm volatile(
        "mma.sync.aligned.m16n8k16.row.col.f32.bf16.bf16.f32 "
        "{%0,%1,%2,%3},{%4,%5,%6,%7},{%8,%9},{%0,%1,%2,%3};"
        : "+f"(c[0]), "+f"(c[1]), "+f"(c[2]), "+f"(c[3])
        : "r"(a[0]), "r"(a[1]), "r"(a[2]), "r"(a[3]), "r"(b[0]), "r"(b[1]));
}

// ---------------- mma.sync GEMM: C(M x noutC) = A3(M x ka) @ W3(noutW x ka)^T ----------------
// 128x128 CTA tile, 8 warps (2M x 4N), K chunks of 64, 3-stage cp.async pipeline,
// single __syncthreads per K-iteration.
static constexpr int GSAS = 72;                  // padded smem stride (elems)
static constexpr int GSEG = 128 * GSAS;          // elems per (matrix) per stage
static constexpr int GSTAGE = 2 * GSEG;          // elems per stage (A+B)
static constexpr int GSMEM_BYTES = 3 * GSTAGE * 2;  // 110592

template <bool GELU, bool SPLIT>
__global__ __launch_bounds__(256)
void mma_gemm(const __nv_bfloat16* __restrict__ A3, int ka,
              const __nv_bfloat16* __restrict__ W3, int noutW,
              const float* __restrict__ bias,
              float* __restrict__ C, int ldc, int M, int noutC,
              __nv_bfloat16* __restrict__ S3) {
    extern __shared__ __align__(16) __nv_bfloat16 smem[];
    int tid = threadIdx.x, lane = tid & 31, wid = tid >> 5;
    int wm = wid & 1, wn = wid >> 1;
    int bm = blockIdx.x * 128, bn = blockIdx.y * 128;
    int NC = ka >> 6;
    uint32_t sU = smem_u32(smem);

    int arow = (lane & 7) + ((lane >> 3) & 1) * 8;
    int acol = ((lane >> 4) & 1) * 8;
    int brow = lane & 7;
    int bk   = ((lane >> 3) & 1) * 8;

    float acc[4][4][4] = {};

#define LOADC(c, slot)                                                                   \
    {                                                                                    \
        int _c64 = (c) * 64;                                                             \
        uint32_t _ab = sU + (slot) * (GSTAGE * 2);                                       \
        uint32_t _bb = _ab + GSEG * 2;                                                   \
        _Pragma("unroll")                                                                \
        for (int _k = 0; _k < 4; _k++) {                                                 \
            int _id = tid + _k * 256;                                                    \
            int _r = _id >> 3, _cg = (_id & 7) * 8;                                      \
            uint32_t _so = (uint32_t)(_r * GSAS + _cg) * 2;                              \
            int _gr = bm + _r; int _pa = _gr < M; int _ga = _pa ? _gr : 0;               \
            cp16(_ab + _so, A3 + (size_t)_ga * ka + _c64 + _cg, _pa);                    \
            int _wr = bn + _r; int _pb = _wr < noutW; int _wa = _pb ? _wr : 0;           \
            cp16(_bb + _so, W3 + (size_t)_wa * ka + _c64 + _cg, _pb);                    \
        }                                                                                \
        cp_commit();                                                                     \
    }

    // prologue: stages 0 and 1
    LOADC(0, 0);
    if (NC > 1) LOADC(1, 1);

    int slot = 0;
    for (int c = 0; c < NC; c++) {
        // wait for stage c (pending groups: c, c+1 -> allow 1 outstanding)
        if (c + 1 < NC) {
            asm volatile("cp.async.wait_group 1;" ::: "memory");
        } else {
            asm volatile("cp.async.wait_group 0;" ::: "memory");
        }
        __syncthreads();
        // prefetch stage c+2 into slot (c+2)%3 == (c-1)%3 (freed: all warps passed compute c-1)
        if (c + 2 < NC) {
            int ns = slot + 2; if (ns >= 3) ns -= 3;
            LOADC(c + 2, ns);
        }
        uint32_t sAb = sU + slot * (GSTAGE * 2);
        uint32_t sBb = sAb + GSEG * 2;
#pragma unroll
        for (int ks = 0; ks < 4; ks++) {
            uint32_t af[4][4];
#pragma unroll
            for (int mf = 0; mf < 4; mf++)
                ldm4(af[mf], sAb + (uint32_t)((wm * 64 + mf * 16 + arow) * GSAS + ks * 16 + acol) * 2);
            uint32_t bf[4][2];
#pragma unroll
            for (int nf = 0; nf < 4; nf++)
                ldm2(bf[nf], sBb + (uint32_t)((wn * 32 + nf * 8 + brow) * GSAS + ks * 16 + bk) * 2);
#pragma unroll
            for (int mf = 0; mf < 4; mf++)
#pragma unroll
                for (int nf = 0; nf < 4; nf++)
                    mma16816(acc[mf][nf], af[mf], bf[nf]);
        }
        slot++; if (slot == 3) slot = 0;
    }
#undef LOADC

    // epilogue
    int cr = lane >> 2, cc = (lane & 3) * 2;
#pragma unroll
    for (int mf = 0; mf < 4; mf++) {
#pragma unroll
        for (int nf = 0; nf < 4; nf++) {
            int col = bn + wn * 32 + nf * 8 + cc;
            if (col >= noutC) continue;
            float bz0 = bias ? bias[col] : 0.f;
            float bz1 = bias ? bias[col + 1] : 0.f;
#pragma unroll
            for (int hh = 0; hh < 2; hh++) {
                int row = bm + wm * 64 + mf * 16 + cr + hh * 8;
                if (row >= M) continue;
                float v0 = acc[mf][nf][hh * 2 + 0] + bz0;
                float v1 = acc[mf][nf][hh * 2 + 1] + bz1;
                if (GELU) {
                    v0 = 0.5f * v0 * (1.0f + erff(v0 * 0.70710678118654752f));
                    v1 = 0.5f * v1 * (1.0f + erff(v1 * 0.70710678118654752f));
                }
                *reinterpret_cast<float2*>(C + (size_t)row * ldc + col) = make_float2(v0, v1);
                if (SPLIT) {
                    size_t b3 = (size_t)row * 3 * noutC;
                    __nv_bfloat16 h0 = __float2bfloat16(v0);
                    __nv_bfloat16 l0 = __float2bfloat16(v0 - __bfloat162float(h0));
                    __nv_bfloat16 h1 = __float2bfloat16(v1);
                    __nv_bfloat16 l1 = __float2bfloat16(v1 - __bfloat162float(h1));
                    S3[b3 + col] = h0; S3[b3 + col + 1] = h1;
                    S3[b3 + noutC + col] = l0; S3[b3 + noutC + col + 1] = l1;
                    S3[b3 + 2 * noutC + col] = h0; S3[b3 + 2 * noutC + col + 1] = h1;
                }
            }
        }
    }
}

// ---------------- pack / conversion ----------------
__global__ void pack_x3_kernel(const float* __restrict__ nf, const float* __restrict__ mem) {
    int idx = blockIdx.x * blockDim.x + threadIdx.x;
    int stride = gridDim.x * blockDim.x;
    for (int i = idx; i < N_ * 256; i += stride) {
        int n = i >> 8, j = i & 255;
        float v = (j < 128) ? nf[n * 128 + j] : mem[n * 128 + (j - 128)];
        __nv_bfloat16 hi = __float2bfloat16(v);
        __nv_bfloat16 lo = __float2bfloat16(v - __bfloat162float(hi));
        size_t b = (size_t)n * 768;
        g_X3[b + j] = hi; g_X3[b + 256 + j] = lo; g_X3[b + 512 + j] = hi;
    }
}

__global__ void pack_b_kernel(const float* __restrict__ wk_b, const float* __restrict__ wv_b,
                              const float* __restrict__ wq_b, const float* __restrict__ wq_w,
                              const float* __restrict__ te_phi) {
    int idx = blockIdx.x * blockDim.x + threadIdx.x;
    if (idx >= 2 * 768) return;
    int l = idx / 768, r = idx % 768;
    float v;
    if (r < 256)      v = wk_b[l * 256 + r];
    else if (r < 512) v = wv_b[l * 256 + (r - 256)];
    else {
        int rq = r - 512;
        v = wq_b[l * 256 + rq];
        for (int t = 0; t < 16; t++) {
            float ph = te_phi[l * 16 + t];
            float qt = (t == 0) ? ph : sinf(ph);
            v += wq_w[(size_t)(l * 256 + rq) * 272 + 256 + t] * qt;
        }
    }
    g_b[idx] = v;
}

__global__ void pack_wall_base_kernel(const float* __restrict__ wk_w, const float* __restrict__ wv_w,
                                      const float* __restrict__ wq_w) {
    int idx = blockIdx.x * blockDim.x + threadIdx.x;
    int stride = gridDim.x * blockDim.x;
    for (int i = idx; i < 2 * 1152 * 256; i += stride) {
        int l = i / (1152 * 256); int r = (i / 256) % 1152; int k = i & 255;
        if (r < 256)      g_Wall[i] = wk_w[(size_t)(l * 256 + r)       * 336 + k];
        else if (r < 512) g_Wall[i] = wv_w[(size_t)(l * 256 + (r-256)) * 336 + k];
        else if (r < 768) g_Wall[i] = wq_w[(size_t)(l * 256 + (r-512)) * 272 + k];
        else if (r >= 1088) g_Wall[i] = 0.f;
    }
    for (int i = idx; i < 2 * 1152; i += stride) {
        int l = i / 1152, r = i % 1152;
        if (r < 768)       g_bias1152[i] = g_b[l * 768 + r];
        else if (r >= 1088) g_bias1152[i] = 0.f;
    }
    for (int i = idx; i < 2 * 256 * 80; i += stride) {
        int l = i / (256 * 80); int r = (i / 80) % 256; int p = i % 80;
        g_Wev[i] = wv_w[(size_t)(l * 256 + r) * 336 + 256 + p];
    }
}

// rows 768..1087 of W_all: (WeTk blockdiag) @ Wq_h, plus cb bias
__global__ __launch_bounds__(256)
void pack_wall_fused_kernel(const float* __restrict__ wk_w, const float* __restrict__ wq_w) {
    __shared__ float wk_s[64];
    int b = blockIdx.x;               // 0..639
    int l = b / 320, q = b % 320;
    int hd = q / 80, p = q % 80;
    int t = threadIdx.x;
    if (t < 64) wk_s[t] = wk_w[(size_t)(l * 256 + 64 * hd + t) * 336 + 256 + p];
    __syncthreads();
    float acc = 0.f;
    for (int c = 0; c < 64; c++)
        acc += wk_s[c] * wq_w[(size_t)(l * 256 + 64 * hd + c) * 272 + t];
    g_Wall[(size_t)l * 1152 * 256 + (size_t)(768 + q) * 256 + t] = acc;
    if (t == 0) {
        float cb = 0.f;
        for (int c = 0; c < 64; c++) cb += wk_s[c] * g_b[l * 768 + 512 + 64 * hd + c];
        g_bias1152[l * 1152 + 768 + q] = cb;
    }
}

// split fp32 (rows x K0) -> bf16 (rows x KA)
__global__ void conv_split_kernel(const float* __restrict__ src, int rows, int K0,
                                  __nv_bfloat16* __restrict__ dst, int KA, int actPat) {
    int idx = blockIdx.x * blockDim.x + threadIdx.x;
    int stride = gridDim.x * blockDim.x;
    long total = (long)rows * KA;
    for (long i = idx; i < total; i += stride) {
        int r = (int)(i / KA); int j = (int)(i % KA);
        __nv_bfloat16 o = __float2bfloat16(0.f);
        int blk = j / K0, jj = j % K0;
        if (blk < 3) {
            float v = src[(size_t)r * K0 + jj];
            __nv_bfloat16 hi = __float2bfloat16(v);
            if (blk == 0) o = hi;
            else {
                __nv_bfloat16 lo = __float2bfloat16(v - __bfloat162float(hi));
                if (actPat) o = (blk == 1) ? lo : hi;
                else        o = (blk == 1) ? hi : lo;
            }
        }
        dst[i] = o;
    }
}

__global__ void zero_agg_kernel() {
    int idx = blockIdx.x * blockDim.x + threadIdx.x;
    if (idx < N_ * 64) reinterpret_cast<float4*>(g_agg)[idx] = make_float4(0.f, 0.f, 0.f, 0.f);
    if (idx < N_ * 20) reinterpret_cast<float4*>(g_aggm)[idx] = make_float4(0.f, 0.f, 0.f, 0.f);
    if (idx < N_) g_nrm[idx] = 0.f;
}

// ---------------- edge attention + scatter (msg computed on the fly) ----------------
__device__ __forceinline__ void red_add4(float* p, float a, float b, float c, float d) {
    asm volatile("red.global.add.v4.f32 [%0], {%1, %2, %3, %4};"
                 :: "l"(p), "f"(a), "f"(b), "f"(c), "f"(d) : "memory");
}

__global__ __launch_bounds__(256)
void edge_attn_kernel(const int* __restrict__ src, const int* __restrict__ dst,
                      const float* __restrict__ ef, const float* __restrict__ et,
                      const float* __restrict__ te_w, const float* __restrict__ te_phi, int l) {
    int e = (blockIdx.x * blockDim.x + threadIdx.x) >> 5;
    int lane = threadIdx.x & 31;
    if (e >= E_) return;
    int s = src[e], d = dst[e];
    int jn = dst[d];                       // faithful h_dst[dst] quirk
    size_t sb = (size_t)s  * 1152;
    size_t jb = (size_t)jn * 1152;
    int o = lane * 8;
    int head = lane >> 3, hl = lane & 7;

    float tv = 0.f;
    {
        float te = et[e];
        if (lane < 16) {
            float wt = -te * te_w[l * 16 + lane] + te_phi[l * 16 + lane];
            tv = (lane == 0) ? wt : sinf(wt);
        }
    }

    float acc = 0.f;
#pragma unroll
    for (int i = 0; i < 8; i += 4) {
        float4 hk = *reinterpret_cast<const float4*>(g_hkvqp + sb + o + i);
        float4 hq = *reinterpret_cast<const float4*>(g_hkvqp + jb + 512 + o + i);
        acc += hk.x * hq.x + hk.y * hq.y + hk.z * hq.z + hk.w * hq.w;
    }
    {
        const float* Pr  = g_hkvqp + jb + 768 + head * 80 + hl;
        const float* efp = ef + (size_t)e * 64 + hl;
#pragma unroll
        for (int t = 0; t < 8; t++) acc += Pr[8 * t] * efp[8 * t];
        float t8 = __shfl_sync(0xffffffffu, tv, hl);
        float t9 = __shfl_sync(0xffffffffu, tv, hl + 8);
        acc += Pr[64] * t8 + Pr[72] * t9;
    }
    acc += __shfl_xor_sync(0xffffffffu, acc, 1);
    acc += __shfl_xor_sync(0xffffffffu, acc, 2);
    acc += __shfl_xor_sync(0xffffffffu, acc, 4);
    float sc = fminf(5.0f, fmaxf(-5.0f, acc * 0.125f));
    float a = __expf(sc);
    float sm = a;
    sm += __shfl_xor_sync(0xffffffffu, sm, 8);
    sm += __shfl_xor_sync(0xffffffffu, sm, 16);
    float af = sm * 0.25f;

    float v[8];
#pragma unroll
    for (int i = 0; i < 8; i += 4) {
        float4 hv = *reinterpret_cast<const float4*>(g_hkvqp + sb + 256 + o + i);
        v[i + 0] = hv.x * af; v[i + 1] = hv.y * af;
        v[i + 2] = hv.z * af; v[i + 3] = hv.w * af;
    }
    float* ag = g_agg + (size_t)d * 256 + o;
    red_add4(ag,     v[0], v[1], v[2], v[3]);
    red_add4(ag + 4, v[4], v[5], v[6], v[7]);

    int bidx = (lane >= 16 && lane < 20) ? (lane - 16) * 4 : 0;
    float s0 = __shfl_sync(0xffffffffu, tv, bidx);
    float s1 = __shfl_sync(0xffffffffu, tv, bidx + 1);
    float s2 = __shfl_sync(0xffffffffu, tv, bidx + 2);
    float s3 = __shfl_sync(0xffffffffu, tv, bidx + 3);
    if (lane < 20) {
        float4 m4;
        if (lane < 16) m4 = *reinterpret_cast<const float4*>(ef + (size_t)e * 64 + lane * 4);
        else           m4 = make_float4(s0, s1, s2, s3);
        red_add4(g_aggm + (size_t)d * 80 + lane * 4, m4.x * af, m4.y * af, m4.z * af, m4.w * af);
    }
    if (lane == 0) atomicAdd(g_nrm + d, af);
}

// ---------------- node update: h = LN(h + LN((agg+agg2)/(nrm+eps))); writes h and h3 ----------------
__global__ __launch_bounds__(256)
void node_update_kernel(const float* __restrict__ aw, const float* __restrict__ ab,
                        const float* __restrict__ lw, const float* __restrict__ lb) {
    int n = (blockIdx.x * blockDim.x + threadIdx.x) >> 5;
    int lane = threadIdx.x & 31;
    if (n >= N_) return;
    size_t base = (size_t)n * 256;
    int o = lane * 8;
    float inv = 1.0f / (g_nrm[n] + 1e-8f);
    float x[8];
    {
        float4 a0 = *reinterpret_cast<const float4*>(g_agg  + base + o);
        float4 a1 = *reinterpret_cast<const float4*>(g_agg  + base + o + 4);
        float4 b0 = *reinterpret_cast<const float4*>(g_agg2 + base + o);
        float4 b1 = *reinterpret_cast<const float4*>(g_agg2 + base + o + 4);
        x[0] = (a0.x + b0.x) * inv; x[1] = (a0.y + b0.y) * inv;
        x[2] = (a0.z + b0.z) * inv; x[3] = (a0.w + b0.w) * inv;
        x[4] = (a1.x + b1.x) * inv; x[5] = (a1.y + b1.y) * inv;
        x[6] = (a1.z + b1.z) * inv; x[7] = (a1.w + b1.w) * inv;
    }
    float s = 0.f;
#pragma unroll
    for (int i = 0; i < 8; i++) s += x[i];
#pragma unroll
    for (int m = 16; m >= 1; m >>= 1) s += __shfl_xor_sync(0xffffffffu, s, m);
    float mean = s * (1.0f / 256.0f);
    float vv = 0.f;
#pragma unroll
    for (int i = 0; i < 8; i++) { float dx = x[i] - mean; vv += dx * dx; }
#pragma unroll
    for (int m = 16; m >= 1; m >>= 1) vv += __shfl_xor_sync(0xffffffffu, vv, m);
    float is = rsqrtf(vv * (1.0f / 256.0f) + 1e-5f);
    float r[8];
#pragma unroll
    for (int i = 0; i < 8; i++) {
        float hn = (x[i] - mean) * is * aw[o + i] + ab[o + i];
        r[i] = g_h[base + o + i] + hn;
    }
    float s2 = 0.f;
#pragma unroll
    for (int i = 0; i < 8; i++) s2 += r[i];
#pragma unroll
    for (int m = 16; m >= 1; m >>= 1) s2 += __shfl_xor_sync(0xffffffffu, s2, m);
    float mean2 = s2 * (1.0f / 256.0f);
    float v2 = 0.f;
#pragma unroll
    for (int i = 0; i < 8; i++) { float dx = r[i] - mean2; v2 += dx * dx; }
#pragma unroll
    for (int m = 16; m >= 1; m >>= 1) v2 += __shfl_xor_sync(0xffffffffu, v2, m);
    float is2 = rsqrtf(v2 * (1.0f / 256.0f) + 1e-5f);
    size_t b3 = (size_t)n * 768;
#pragma unroll
    for (int i = 0; i < 8; i++) {
        float hv = (r[i] - mean2) * is2 * lw[o + i] + lb[o + i];
        g_h[base + o + i] = hv;
        __nv_bfloat16 hi = __float2bfloat16(hv);
        __nv_bfloat16 lo = __float2bfloat16(hv - __bfloat162float(hi));
        g_h3[b3 + o + i] = hi;
        g_h3[b3 + 256 + o + i] = lo;
        g_h3[b3 + 512 + o + i] = hi;
    }
}

// ---------------- launch ----------------
extern "C" void kernel_launch(void* const* d_in, const int* in_sizes, int n_in,
                              void* d_out, int out_size) {
    const float* node_feat  = (const float*)d_in[0];
    const float* memory     = (const float*)d_in[1];
    const int*   eidx       = (const int*)  d_in[2];
    const float* edge_feat  = (const float*)d_in[3];
    const float* edge_times = (const float*)d_in[4];
    const float* in_w       = (const float*)d_in[5];
    const float* in_b       = (const float*)d_in[6];
    const float* te_w       = (const float*)d_in[7];
    const float* te_phi     = (const float*)d_in[8];
    const float* wq_w       = (const float*)d_in[9];
    const float* wq_b       = (const float*)d_in[10];
    const float* wk_w       = (const float*)d_in[11];
    const float* wk_b       = (const float*)d_in[12];
    const float* wv_w       = (const float*)d_in[13];
    const float* wv_b       = (const float*)d_in[14];
    const float* attn_ln_w  = (const float*)d_in[15];
    const float* attn_ln_b  = (const float*)d_in[16];
    const float* ln_w       = (const float*)d_in[17];
    const float* ln_b       = (const float*)d_in[18];
    const float* out_w      = (const float*)d_in[19];
    const float* out_b      = (const float*)d_in[20];
    const int* src = eidx;
    const int* dst = eidx + E_;
    float* out = (float*)d_out;

    float *ph, *phkvqp, *pAggm, *pAgg2, *pWall, *pWev, *pBias;
    __nv_bfloat16 *pX3, *ph3, *pAggm3, *pWall3, *pWin3, *pWev3, *pWout3;
    cudaGetSymbolAddress((void**)&ph,     g_h);
    cudaGetSymbolAddress((void**)&phkvqp, g_hkvqp);
    cudaGetSymbolAddress((void**)&pAggm,  g_aggm);
    cudaGetSymbolAddress((void**)&pAgg2,  g_agg2);
    cudaGetSymbolAddress((void**)&pWall,  g_Wall);
    cudaGetSymbolAddress((void**)&pWev,   g_Wev);
    cudaGetSymbolAddress((void**)&pBias,  g_bias1152);
    cudaGetSymbolAddress((void**)&pX3,    g_X3);
    cudaGetSymbolAddress((void**)&ph3,    g_h3);
    cudaGetSymbolAddress((void**)&pAggm3, g_aggm3);
    cudaGetSymbolAddress((void**)&pWall3, g_Wall3);
    cudaGetSymbolAddress((void**)&pWin3,  g_Win3);
    cudaGetSymbolAddress((void**)&pWev3,  g_Wev3);
    cudaGetSymbolAddress((void**)&pWout3, g_Wout3);

    cudaFuncSetAttribute(mma_gemm<false, true>,  cudaFuncAttributeMaxDynamicSharedMemorySize, GSMEM_BYTES);
    cudaFuncSetAttribute(mma_gemm<false, false>, cudaFuncAttributeMaxDynamicSharedMemorySize, GSMEM_BYTES);
    cudaFuncSetAttribute(mma_gemm<true, false>,  cudaFuncAttributeMaxDynamicSharedMemorySize, GSMEM_BYTES);

    const int GX = (N_ + 127) / 128;  // 391

    pack_x3_kernel<<<4096, 256>>>(node_feat, memory);
    pack_b_kernel<<<6, 256>>>(wk_b, wv_b, wq_b, wq_w, te_phi);
    pack_wall_base_kernel<<<2304, 256>>>(wk_w, wv_w, wq_w);
    pack_wall_fused_kernel<<<640, 256>>>(wk_w, wq_w);
    conv_split_kernel<<<4096, 256>>>(pWall, 2 * 1152, 256, pWall3, 768, 0);
    conv_split_kernel<<<768, 256>>>((const float*)in_w, 256, 256, pWin3, 768, 0);
    conv_split_kernel<<<192, 256>>>((const float*)out_w, 64, 256, pWout3, 768, 0);
    conv_split_kernel<<<512, 256>>>(pWev, 2 * 256, 80, pWev3, 256, 0);

    // h = X @ in_w^T + in_b (also emits h3 split)
    mma_gemm<false, true><<<dim3(GX, 2), 256, GSMEM_BYTES>>>(pX3, 768, pWin3, 256, in_b,
                                                             ph, 256, N_, 256, ph3);

    for (int l = 0; l < 2; l++) {
        // [K'|V'|Q'|P] = h @ W_all^T + [bk|bv|bq_eff|cb]
        mma_gemm<false, false><<<dim3(GX, 9), 256, GSMEM_BYTES>>>(
            ph3, 768, pWall3 + (size_t)l * 1152 * 768, 1152,
            pBias + l * 1152, phkvqp, 1152, N_, 1088, nullptr);
        zero_agg_kernel<<<12500, 256>>>();
        edge_attn_kernel<<<25000, 256>>>(src, dst, edge_feat, edge_times, te_w, te_phi, l);
        conv_split_kernel<<<4096, 256>>>(pAggm, N_, 80, pAggm3, 256, 1);
        // agg2 = aggm @ We_v^T
        mma_gemm<false, false><<<dim3(GX, 2), 256, GSMEM_BYTES>>>(
            pAggm3, 256, pWev3 + (size_t)l * 256 * 256, 256,
            nullptr, pAgg2, 256, N_, 256, nullptr);
        node_update_kernel<<<6250, 256>>>(attn_ln_w + l * 256, attn_ln_b + l * 256,
                                          ln_w + l * 256, ln_b + l * 256);
    }

    // out = gelu(h @ out_w^T + out_b)
    mma_gemm<true, false><<<dim3(GX, 1), 256, GSMEM_BYTES>>>(ph3, 768, pWout3, 64, out_b,
                                                             out, 64, N_, 64, nullptr);
}

// round 9
// speedup vs baseline: 1.1595x; 1.1595x over previous
#include <cuda_runtime.h>
#include <cuda_bf16.h>
#include <math.h>
#include <stdint.h>

static constexpr int N_ = 50000;
static constexpr int E_ = 200000;

// ---------------- scratch ----------------
__device__ __nv_bfloat16 g_X3   [(size_t)N_ * 768];   // split [hi|lo|hi] of [nf|mem]
__device__ float         g_h    [(size_t)N_ * 256];
__device__ __nv_bfloat16 g_h3   [(size_t)N_ * 768];   // split of h
__device__ float         g_hkvqp[(size_t)N_ * 1152];  // [K'|V'|Q'|P(320)|pad] (biases folded)
__device__ float         g_agg  [(size_t)N_ * 256];
__device__ float         g_agg2 [(size_t)N_ * 256];
__device__ __nv_bfloat16 g_aggm3[(size_t)N_ * 256];   // bf16 split of aggm (K0=80 pad 256)
__device__ float         g_nrm  [N_];
__device__ float         g_Wall [2 * 1152 * 256];     // fp32 [Wk;Wv;Wq;Wfused;0]
__device__ __nv_bfloat16 g_Wall3[2 * 1152 * 768];
__device__ float         g_bias1152[2 * 1152];        // [bk|bv|bq_eff|cb|0]
__device__ __nv_bfloat16 g_Win3 [256 * 768];
__device__ float         g_Wev  [2 * 256 * 80];
__device__ __nv_bfloat16 g_Wev3 [2 * 256 * 256];
__device__ __nv_bfloat16 g_Wout3[64 * 768];
__device__ float         g_b    [2 * 768];            // [bk|bv|bq_eff]
// CSR
__device__ int g_off [N_ + 1];
__device__ int g_cnt [N_];
__device__ int g_eid [E_];

// ---------------- ptx helpers (family-safe, sm_80 baseline) ----------------
__device__ __forceinline__ uint32_t smem_u32(const void* p) {
    uint32_t a;
    asm("{ .reg .u64 t; cvta.to.shared.u64 t, %1; cvt.u32.u64 %0, t; }" : "=r"(a) : "l"(p));
    return a;
}
__device__ __forceinline__ void cp16(uint32_t dst, const void* src, int pred) {
    asm volatile(
        "{\n\t.reg .pred p;\n\t"
        "setp.ne.u32 p, %2, 0;\n\t"
        "@p cp.async.ca.shared.global [%0], [%1], 16;\n\t"
        "@!p cp.async.ca.shared.global [%0], [%1], 16, 0;\n\t}"
        :: "r"(dst), "l"(src), "r"(pred) : "memory");
}
__device__ __forceinline__ void cp_commit() {
    asm volatile("cp.async.commit_group;" ::: "memory");
}
__device__ __forceinline__ void ldm4(uint32_t* r, uint32_t addr) {
    asm volatile("ldmatrix.sync.aligned.m8n8.x4.shared.b16 {%0,%1,%2,%3}, [%4];"
                 : "=r"(r[0]), "=r"(r[1]), "=r"(r[2]), "=r"(r[3]) : "r"(addr));
}
__device__ __forceinline__ void ldm2(uint32_t* r, uint32_t addr) {
    asm volatile("ldmatrix.sync.aligned.m8n8.x2.shared.b16 {%0,%1}, [%2];"
                 : "=r"(r[0]), "=r"(r[1]) : "r"(addr));
}
__device__ __forceinline__ void mma16816(float* c, const uint32_t* a, const uint32_t* b) {
    asm volatile(
        "mma.sync.aligned.m16n8k16.row.col.f32.bf16.bf16.f32 "
        "{%0,%1,%2,%3},{%4,%5,%6,%7},{%8,%9},{%0,%1,%2,%3};"
        : "+f"(c[0]), "+f"(c[1]), "+f"(c[2]), "+f"(c[3])
        : "r"(a[0]), "r"(a[1]), "r"(a[2]), "r"(a[3]), "r"(b[0]), "r"(b[1]));
}

// ---------------- mma.sync GEMM (R5 double-buffered, K chunks of 64) ----------------
static constexpr int GSAS = 72;
static constexpr int GSEG = 128 * GSAS;
static constexpr int GSMEM_BYTES = 4 * GSEG * 2;  // 73728

template <bool GELU, bool SPLIT>
__global__ __launch_bounds__(256)
void mma_gemm(const __nv_bfloat16* __restrict__ A3, int ka,
              const __nv_bfloat16* __restrict__ W3, int noutW,
              const float* __restrict__ bias,
              float* __restrict__ C, int ldc, int M, int noutC,
              __nv_bfloat16* __restrict__ S3) {
    extern __shared__ __align__(16) __nv_bfloat16 smem[];
    int tid = threadIdx.x, lane = tid & 31, wid = tid >> 5;
    int wm = wid & 1, wn = wid >> 1;
    int bm = blockIdx.x * 128, bn = blockIdx.y * 128;
    int NC = ka >> 6;
    uint32_t sU = smem_u32(smem);

    int arow = (lane & 7) + ((lane >> 3) & 1) * 8;
    int acol = ((lane >> 4) & 1) * 8;
    int brow = lane & 7;
    int bk   = ((lane >> 3) & 1) * 8;

    float acc[4][4][4] = {};

#define LOADC(c, buf)                                                                    \
    {                                                                                    \
        int _c64 = (c) * 64;                                                             \
        uint32_t _ab = sU + (buf) * (2 * GSEG * 2);                                      \
        uint32_t _bb = _ab + GSEG * 2;                                                   \
        _Pragma("unroll")                                                                \
        for (int _k = 0; _k < 4; _k++) {                                                 \
            int _id = tid + _k * 256;                                                    \
            int _r = _id >> 3, _cg = (_id & 7) * 8;                                      \
            uint32_t _so = (uint32_t)(_r * GSAS + _cg) * 2;                              \
            int _gr = bm + _r; int _pa = _gr < M; int _ga = _pa ? _gr : 0;               \
            cp16(_ab + _so, A3 + (size_t)_ga * ka + _c64 + _cg, _pa);                    \
            int _wr = bn + _r; int _pb = _wr < noutW; int _wa = _pb ? _wr : 0;           \
            cp16(_bb + _so, W3 + (size_t)_wa * ka + _c64 + _cg, _pb);                    \
        }                                                                                \
        cp_commit();                                                                     \
    }

    LOADC(0, 0);
    for (int c = 0; c < NC; c++) {
        if (c + 1 < NC) {
            LOADC(c + 1, (c + 1) & 1);
            asm volatile("cp.async.wait_group 1;" ::: "memory");
        } else {
            asm volatile("cp.async.wait_group 0;" ::: "memory");
        }
        __syncthreads();
        uint32_t sAb = sU + (c & 1) * (2 * GSEG * 2);
        uint32_t sBb = sAb + GSEG * 2;
#pragma unroll
        for (int ks = 0; ks < 4; ks++) {
            uint32_t af[4][4];
#pragma unroll
            for (int mf = 0; mf < 4; mf++)
                ldm4(af[mf], sAb + (uint32_t)((wm * 64 + mf * 16 + arow) * GSAS + ks * 16 + acol) * 2);
            uint32_t bf[4][2];
#pragma unroll
            for (int nf = 0; nf < 4; nf++)
                ldm2(bf[nf], sBb + (uint32_t)((wn * 32 + nf * 8 + brow) * GSAS + ks * 16 + bk) * 2);
#pragma unroll
            for (int mf = 0; mf < 4; mf++)
#pragma unroll
                for (int nf = 0; nf < 4; nf++)
                    mma16816(acc[mf][nf], af[mf], bf[nf]);
        }
        __syncthreads();
    }
#undef LOADC

    int cr = lane >> 2, cc = (lane & 3) * 2;
#pragma unroll
    for (int mf = 0; mf < 4; mf++) {
#pragma unroll
        for (int nf = 0; nf < 4; nf++) {
            int col = bn + wn * 32 + nf * 8 + cc;
            if (col >= noutC) continue;
            float bz0 = bias ? bias[col] : 0.f;
            float bz1 = bias ? bias[col + 1] : 0.f;
#pragma unroll
            for (int hh = 0; hh < 2; hh++) {
                int row = bm + wm * 64 + mf * 16 + cr + hh * 8;
                if (row >= M) continue;
                float v0 = acc[mf][nf][hh * 2 + 0] + bz0;
                float v1 = acc[mf][nf][hh * 2 + 1] + bz1;
                if (GELU) {
                    v0 = 0.5f * v0 * (1.0f + erff(v0 * 0.70710678118654752f));
                    v1 = 0.5f * v1 * (1.0f + erff(v1 * 0.70710678118654752f));
                }
                *reinterpret_cast<float2*>(C + (size_t)row * ldc + col) = make_float2(v0, v1);
                if (SPLIT) {
                    size_t b3 = (size_t)row * 3 * noutC;
                    __nv_bfloat16 h0 = __float2bfloat16(v0);
                    __nv_bfloat16 l0 = __float2bfloat16(v0 - __bfloat162float(h0));
                    __nv_bfloat16 h1 = __float2bfloat16(v1);
                    __nv_bfloat16 l1 = __float2bfloat16(v1 - __bfloat162float(h1));
                    S3[b3 + col] = h0; S3[b3 + col + 1] = h1;
                    S3[b3 + noutC + col] = l0; S3[b3 + noutC + col + 1] = l1;
                    S3[b3 + 2 * noutC + col] = h0; S3[b3 + 2 * noutC + col + 1] = h1;
                }
            }
        }
    }
}

// ---------------- pack / conversion ----------------
__global__ void pack_x3_kernel(const float* __restrict__ nf, const float* __restrict__ mem) {
    int idx = blockIdx.x * blockDim.x + threadIdx.x;
    int stride = gridDim.x * blockDim.x;
    for (int i = idx; i < N_ * 256; i += stride) {
        int n = i >> 8, j = i & 255;
        float v = (j < 128) ? nf[n * 128 + j] : mem[n * 128 + (j - 128)];
        __nv_bfloat16 hi = __float2bfloat16(v);
        __nv_bfloat16 lo = __float2bfloat16(v - __bfloat162float(hi));
        size_t b = (size_t)n * 768;
        g_X3[b + j] = hi; g_X3[b + 256 + j] = lo; g_X3[b + 512 + j] = hi;
    }
}

__global__ void pack_b_kernel(const float* __restrict__ wk_b, const float* __restrict__ wv_b,
                              const float* __restrict__ wq_b, const float* __restrict__ wq_w,
                              const float* __restrict__ te_phi) {
    int idx = blockIdx.x * blockDim.x + threadIdx.x;
    if (idx >= 2 * 768) return;
    int l = idx / 768, r = idx % 768;
    float v;
    if (r < 256)      v = wk_b[l * 256 + r];
    else if (r < 512) v = wv_b[l * 256 + (r - 256)];
    else {
        int rq = r - 512;
        v = wq_b[l * 256 + rq];
        for (int t = 0; t < 16; t++) {
            float ph = te_phi[l * 16 + t];
            float qt = (t == 0) ? ph : sinf(ph);
            v += wq_w[(size_t)(l * 256 + rq) * 272 + 256 + t] * qt;
        }
    }
    g_b[idx] = v;
}

__global__ void pack_wall_base_kernel(const float* __restrict__ wk_w, const float* __restrict__ wv_w,
                                      const float* __restrict__ wq_w) {
    int idx = blockIdx.x * blockDim.x + threadIdx.x;
    int stride = gridDim.x * blockDim.x;
    for (int i = idx; i < 2 * 1152 * 256; i += stride) {
        int l = i / (1152 * 256); int r = (i / 256) % 1152; int k = i & 255;
        if (r < 256)      g_Wall[i] = wk_w[(size_t)(l * 256 + r)       * 336 + k];
        else if (r < 512) g_Wall[i] = wv_w[(size_t)(l * 256 + (r-256)) * 336 + k];
        else if (r < 768) g_Wall[i] = wq_w[(size_t)(l * 256 + (r-512)) * 272 + k];
        else if (r >= 1088) g_Wall[i] = 0.f;
    }
    for (int i = idx; i < 2 * 1152; i += stride) {
        int l = i / 1152, r = i % 1152;
        if (r < 768)       g_bias1152[i] = g_b[l * 768 + r];
        else if (r >= 1088) g_bias1152[i] = 0.f;
    }
    for (int i = idx; i < 2 * 256 * 80; i += stride) {
        int l = i / (256 * 80); int r = (i / 80) % 256; int p = i % 80;
        g_Wev[i] = wv_w[(size_t)(l * 256 + r) * 336 + 256 + p];
    }
}

__global__ __launch_bounds__(256)
void pack_wall_fused_kernel(const float* __restrict__ wk_w, const float* __restrict__ wq_w) {
    __shared__ float wk_s[64];
    int b = blockIdx.x;               // 0..639
    int l = b / 320, q = b % 320;
    int hd = q / 80, p = q % 80;
    int t = threadIdx.x;
    if (t < 64) wk_s[t] = wk_w[(size_t)(l * 256 + 64 * hd + t) * 336 + 256 + p];
    __syncthreads();
    float acc = 0.f;
    for (int c = 0; c < 64; c++)
        acc += wk_s[c] * wq_w[(size_t)(l * 256 + 64 * hd + c) * 272 + t];
    g_Wall[(size_t)l * 1152 * 256 + (size_t)(768 + q) * 256 + t] = acc;
    if (t == 0) {
        float cb = 0.f;
        for (int c = 0; c < 64; c++) cb += wk_s[c] * g_b[l * 768 + 512 + 64 * hd + c];
        g_bias1152[l * 1152 + 768 + q] = cb;
    }
}

__global__ void conv_split_kernel(const float* __restrict__ src, int rows, int K0,
                                  __nv_bfloat16* __restrict__ dst, int KA, int actPat) {
    int idx = blockIdx.x * blockDim.x + threadIdx.x;
    int stride = gridDim.x * blockDim.x;
    long total = (long)rows * KA;
    for (long i = idx; i < total; i += stride) {
        int r = (int)(i / KA); int j = (int)(i % KA);
        __nv_bfloat16 o = __float2bfloat16(0.f);
        int blk = j / K0, jj = j % K0;
        if (blk < 3) {
            float v = src[(size_t)r * K0 + jj];
            __nv_bfloat16 hi = __float2bfloat16(v);
            if (blk == 0) o = hi;
            else {
                __nv_bfloat16 lo = __float2bfloat16(v - __bfloat162float(hi));
                if (actPat) o = (blk == 1) ? lo : hi;
                else        o = (blk == 1) ? hi : lo;
            }
        }
        dst[i] = o;
    }
}

// ---------------- CSR build ----------------
__global__ void csr_zero_kernel() {
    int i = blockIdx.x * blockDim.x + threadIdx.x;
    if (i < N_) g_cnt[i] = 0;
}
__global__ void csr_count_kernel(const int* __restrict__ dst) {
    int e = blockIdx.x * blockDim.x + threadIdx.x;
    if (e < E_) atomicAdd(&g_cnt[dst[e]], 1);
}
__global__ __launch_bounds__(1024)
void csr_scan_kernel() {
    __shared__ int sh[1024];
    int tid = threadIdx.x;
    const int CH = (N_ + 1023) / 1024;   // 49
    int lo = tid * CH, hi = min(lo + CH, N_);
    int s = 0;
    for (int i = lo; i < hi; i++) s += g_cnt[i];
    sh[tid] = s;
    __syncthreads();
    for (int ofs = 1; ofs < 1024; ofs <<= 1) {
        int v = (tid >= ofs) ? sh[tid - ofs] : 0;
        __syncthreads();
        sh[tid] += v;
        __syncthreads();
    }
    int run = sh[tid] - s;   // exclusive prefix
    for (int i = lo; i < hi; i++) {
        g_off[i] = run;
        run += g_cnt[i];
        g_cnt[i] = 0;        // reset as fill cursor
    }
    if (tid == 1023) g_off[N_] = sh[1023];
}
__global__ void csr_fill_kernel(const int* __restrict__ dst) {
    int e = blockIdx.x * blockDim.x + threadIdx.x;
    if (e >= E_) return;
    int d = dst[e];
    int pos = atomicAdd(&g_cnt[d], 1);
    g_eid[g_off[d] + pos] = e;
}

// ---------------- node-centric attention (gather, no atomics) ----------------
__global__ __launch_bounds__(256)
void node_attn_kernel(const int* __restrict__ src, const int* __restrict__ dst,
                      const float* __restrict__ ef, const float* __restrict__ et,
                      const float* __restrict__ te_w, const float* __restrict__ te_phi, int l) {
    int d = (blockIdx.x * blockDim.x + threadIdx.x) >> 5;
    int lane = threadIdx.x & 31;
    if (d >= N_) return;
    int jn = dst[d];                       // faithful h_dst[dst] quirk
    size_t jb = (size_t)jn * 1152;
    int o = lane * 8;
    int hl = lane & 7;

    // per-node Q' and P (loaded once)
    float q[8];
    {
        float4 q0 = *reinterpret_cast<const float4*>(g_hkvqp + jb + 512 + o);
        float4 q1 = *reinterpret_cast<const float4*>(g_hkvqp + jb + 512 + o + 4);
        q[0]=q0.x; q[1]=q0.y; q[2]=q0.z; q[3]=q0.w; q[4]=q1.x; q[5]=q1.y; q[6]=q1.z; q[7]=q1.w;
    }
    float Pv[10];
    {
        const float* Pr = g_hkvqp + jb + 768 + (lane >> 3) * 80 + hl;
#pragma unroll
        for (int t = 0; t < 10; t++) Pv[t] = Pr[8 * t];
    }
    float tw = 0.f, tph = 0.f;
    if (lane < 16) { tw = te_w[l * 16 + lane]; tph = te_phi[l * 16 + lane]; }

    float aggv[8] = {};
    float am0 = 0.f, am1 = 0.f, am2 = 0.f;
    float nrm = 0.f;

    int beg = g_off[d], end = g_off[d + 1];
    for (int ii = beg; ii < end; ii++) {
        int e = g_eid[ii];
        int s = src[e];
        size_t sb = (size_t)s * 1152;
        const float* efp = ef + (size_t)e * 64;

        float tv = 0.f;
        {
            float te = et[e];
            if (lane < 16) {
                float wt = -te * tw + tph;
                tv = (lane == 0) ? wt : sinf(wt);
            }
        }
        // score: Q'.K' + P . [ef|tenc]
        float acc = 0.f;
        {
            float4 hk0 = *reinterpret_cast<const float4*>(g_hkvqp + sb + o);
            float4 hk1 = *reinterpret_cast<const float4*>(g_hkvqp + sb + o + 4);
            acc += hk0.x * q[0] + hk0.y * q[1] + hk0.z * q[2] + hk0.w * q[3];
            acc += hk1.x * q[4] + hk1.y * q[5] + hk1.z * q[6] + hk1.w * q[7];
        }
#pragma unroll
        for (int t = 0; t < 8; t++) acc += Pv[t] * efp[hl + 8 * t];
        float t8 = __shfl_sync(0xffffffffu, tv, hl);
        float t9 = __shfl_sync(0xffffffffu, tv, hl + 8);
        acc += Pv[8] * t8 + Pv[9] * t9;

        acc += __shfl_xor_sync(0xffffffffu, acc, 1);
        acc += __shfl_xor_sync(0xffffffffu, acc, 2);
        acc += __shfl_xor_sync(0xffffffffu, acc, 4);
        float sc = fminf(5.0f, fmaxf(-5.0f, acc * 0.125f));
        float a = __expf(sc);
        float sm = a;
        sm += __shfl_xor_sync(0xffffffffu, sm, 8);
        sm += __shfl_xor_sync(0xffffffffu, sm, 16);
        float af = sm * 0.25f;

        // accumulate V' and msg
        {
            float4 hv0 = *reinterpret_cast<const float4*>(g_hkvqp + sb + 256 + o);
            float4 hv1 = *reinterpret_cast<const float4*>(g_hkvqp + sb + 256 + o + 4);
            aggv[0] += hv0.x * af; aggv[1] += hv0.y * af; aggv[2] += hv0.z * af; aggv[3] += hv0.w * af;
            aggv[4] += hv1.x * af; aggv[5] += hv1.y * af; aggv[6] += hv1.z * af; aggv[7] += hv1.w * af;
        }
        am0 += efp[lane] * af;
        am1 += efp[32 + lane] * af;
        if (lane < 16) am2 += tv * af;
        nrm += af;
    }

    // write agg (fp32), nrm, aggm3 (bf16 split [hi|lo|hi] over K0=80 pad 256)
    size_t base = (size_t)d * 256;
    *reinterpret_cast<float4*>(g_agg + base + o)     = make_float4(aggv[0], aggv[1], aggv[2], aggv[3]);
    *reinterpret_cast<float4*>(g_agg + base + o + 4) = make_float4(aggv[4], aggv[5], aggv[6], aggv[7]);
    if (lane == 0) g_nrm[d] = nrm;

    __nv_bfloat16* am3 = g_aggm3 + base;
    {
        __nv_bfloat16 h0 = __float2bfloat16(am0);
        __nv_bfloat16 l0 = __float2bfloat16(am0 - __bfloat162float(h0));
        am3[lane] = h0; am3[lane + 80] = l0; am3[lane + 160] = h0;
        __nv_bfloat16 h1 = __float2bfloat16(am1);
        __nv_bfloat16 l1 = __float2bfloat16(am1 - __bfloat162float(h1));
        am3[32 + lane] = h1; am3[32 + lane + 80] = l1; am3[32 + lane + 160] = h1;
        if (lane < 16) {
            __nv_bfloat16 h2 = __float2bfloat16(am2);
            __nv_bfloat16 l2 = __float2bfloat16(am2 - __bfloat162float(h2));
            am3[64 + lane] = h2; am3[64 + lane + 80] = l2; am3[64 + lane + 160] = h2;
            am3[240 + lane] = __float2bfloat16(0.f);
        }
    }
}

// ---------------- node update: h = LN(h + LN((agg+agg2)/(nrm+eps))); writes h and h3 ----------------
__global__ __launch_bounds__(256)
void node_update_kernel(const float* __restrict__ aw, const float* __restrict__ ab,
                        const float* __restrict__ lw, const float* __restrict__ lb) {
    int n = (blockIdx.x * blockDim.x + threadIdx.x) >> 5;
    int lane = threadIdx.x & 31;
    if (n >= N_) return;
    size_t base = (size_t)n * 256;
    int o = lane * 8;
    float inv = 1.0f / (g_nrm[n] + 1e-8f);
    float x[8];
    {
        float4 a0 = *reinterpret_cast<const float4*>(g_agg  + base + o);
        float4 a1 = *reinterpret_cast<const float4*>(g_agg  + base + o + 4);
        float4 b0 = *reinterpret_cast<const float4*>(g_agg2 + base + o);
        float4 b1 = *reinterpret_cast<const float4*>(g_agg2 + base + o + 4);
        x[0] = (a0.x + b0.x) * inv; x[1] = (a0.y + b0.y) * inv;
        x[2] = (a0.z + b0.z) * inv; x[3] = (a0.w + b0.w) * inv;
        x[4] = (a1.x + b1.x) * inv; x[5] = (a1.y + b1.y) * inv;
        x[6] = (a1.z + b1.z) * inv; x[7] = (a1.w + b1.w) * inv;
    }
    float s = 0.f;
#pragma unroll
    for (int i = 0; i < 8; i++) s += x[i];
#pragma unroll
    for (int m = 16; m >= 1; m >>= 1) s += __shfl_xor_sync(0xffffffffu, s, m);
    float mean = s * (1.0f / 256.0f);
    float vv = 0.f;
#pragma unroll
    for (int i = 0; i < 8; i++) { float dx = x[i] - mean; vv += dx * dx; }
#pragma unroll
    for (int m = 16; m >= 1; m >>= 1) vv += __shfl_xor_sync(0xffffffffu, vv, m);
    float is = rsqrtf(vv * (1.0f / 256.0f) + 1e-5f);
    float r[8];
#pragma unroll
    for (int i = 0; i < 8; i++) {
        float hn = (x[i] - mean) * is * aw[o + i] + ab[o + i];
        r[i] = g_h[base + o + i] + hn;
    }
    float s2 = 0.f;
#pragma unroll
    for (int i = 0; i < 8; i++) s2 += r[i];
#pragma unroll
    for (int m = 16; m >= 1; m >>= 1) s2 += __shfl_xor_sync(0xffffffffu, s2, m);
    float mean2 = s2 * (1.0f / 256.0f);
    float v2 = 0.f;
#pragma unroll
    for (int i = 0; i < 8; i++) { float dx = r[i] - mean2; v2 += dx * dx; }
#pragma unroll
    for (int m = 16; m >= 1; m >>= 1) v2 += __shfl_xor_sync(0xffffffffu, v2, m);
    float is2 = rsqrtf(v2 * (1.0f / 256.0f) + 1e-5f);
    size_t b3 = (size_t)n * 768;
#pragma unroll
    for (int i = 0; i < 8; i++) {
        float hv = (r[i] - mean2) * is2 * lw[o + i] + lb[o + i];
        g_h[base + o + i] = hv;
        __nv_bfloat16 hi = __float2bfloat16(hv);
        __nv_bfloat16 lo = __float2bfloat16(hv - __bfloat162float(hi));
        g_h3[b3 + o + i] = hi;
        g_h3[b3 + 256 + o + i] = lo;
        g_h3[b3 + 512 + o + i] = hi;
    }
}

// ---------------- launch ----------------
extern "C" void kernel_launch(void* const* d_in, const int* in_sizes, int n_in,
                              void* d_out, int out_size) {
    const float* node_feat  = (const float*)d_in[0];
    const float* memory     = (const float*)d_in[1];
    const int*   eidx       = (const int*)  d_in[2];
    const float* edge_feat  = (const float*)d_in[3];
    const float* edge_times = (const float*)d_in[4];
    const float* in_w       = (const float*)d_in[5];
    const float* in_b       = (const float*)d_in[6];
    const float* te_w       = (const float*)d_in[7];
    const float* te_phi     = (const float*)d_in[8];
    const float* wq_w       = (const float*)d_in[9];
    const float* wq_b       = (const float*)d_in[10];
    const float* wk_w       = (const float*)d_in[11];
    const float* wk_b       = (const float*)d_in[12];
    const float* wv_w       = (const float*)d_in[13];
    const float* wv_b       = (const float*)d_in[14];
    const float* attn_ln_w  = (const float*)d_in[15];
    const float* attn_ln_b  = (const float*)d_in[16];
    const float* ln_w       = (const float*)d_in[17];
    const float* ln_b       = (const float*)d_in[18];
    const float* out_w      = (const float*)d_in[19];
    const float* out_b      = (const float*)d_in[20];
    const int* src = eidx;
    const int* dst = eidx + E_;
    float* out = (float*)d_out;

    float *ph, *phkvqp, *pAgg2, *pWall, *pWev, *pBias;
    __nv_bfloat16 *pX3, *ph3, *pAggm3, *pWall3, *pWin3, *pWev3, *pWout3;
    cudaGetSymbolAddress((void**)&ph,     g_h);
    cudaGetSymbolAddress((void**)&phkvqp, g_hkvqp);
    cudaGetSymbolAddress((void**)&pAgg2,  g_agg2);
    cudaGetSymbolAddress((void**)&pWall,  g_Wall);
    cudaGetSymbolAddress((void**)&pWev,   g_Wev);
    cudaGetSymbolAddress((void**)&pBias,  g_bias1152);
    cudaGetSymbolAddress((void**)&pX3,    g_X3);
    cudaGetSymbolAddress((void**)&ph3,    g_h3);
    cudaGetSymbolAddress((void**)&pAggm3, g_aggm3);
    cudaGetSymbolAddress((void**)&pWall3, g_Wall3);
    cudaGetSymbolAddress((void**)&pWin3,  g_Win3);
    cudaGetSymbolAddress((void**)&pWev3,  g_Wev3);
    cudaGetSymbolAddress((void**)&pWout3, g_Wout3);

    cudaFuncSetAttribute(mma_gemm<false, true>,  cudaFuncAttributeMaxDynamicSharedMemorySize, GSMEM_BYTES);
    cudaFuncSetAttribute(mma_gemm<false, false>, cudaFuncAttributeMaxDynamicSharedMemorySize, GSMEM_BYTES);
    cudaFuncSetAttribute(mma_gemm<true, false>,  cudaFuncAttributeMaxDynamicSharedMemorySize, GSMEM_BYTES);

    const int GX = (N_ + 127) / 128;  // 391

    pack_x3_kernel<<<4096, 256>>>(node_feat, memory);
    pack_b_kernel<<<6, 256>>>(wk_b, wv_b, wq_b, wq_w, te_phi);
    pack_wall_base_kernel<<<2304, 256>>>(wk_w, wv_w, wq_w);
    pack_wall_fused_kernel<<<640, 256>>>(wk_w, wq_w);
    conv_split_kernel<<<4096, 256>>>(pWall, 2 * 1152, 256, pWall3, 768, 0);
    conv_split_kernel<<<768, 256>>>((const float*)in_w, 256, 256, pWin3, 768, 0);
    conv_split_kernel<<<192, 256>>>((const float*)out_w, 64, 256, pWout3, 768, 0);
    conv_split_kernel<<<512, 256>>>(pWev, 2 * 256, 80, pWev3, 256, 0);

    // CSR build (topology is layer-independent)
    csr_zero_kernel<<<(N_ + 255) / 256, 256>>>();
    csr_count_kernel<<<(E_ + 255) / 256, 256>>>(dst);
    csr_scan_kernel<<<1, 1024>>>();
    csr_fill_kernel<<<(E_ + 255) / 256, 256>>>(dst);

    // h = X @ in_w^T + in_b (also emits h3 split)
    mma_gemm<false, true><<<dim3(GX, 2), 256, GSMEM_BYTES>>>(pX3, 768, pWin3, 256, in_b,
                                                             ph, 256, N_, 256, ph3);

    for (int l = 0; l < 2; l++) {
        // [K'|V'|Q'|P] = h @ W_all^T + [bk|bv|bq_eff|cb]
        mma_gemm<false, false><<<dim3(GX, 9), 256, GSMEM_BYTES>>>(
            ph3, 768, pWall3 + (size_t)l * 1152 * 768, 1152,
            pBias + l * 1152, phkvqp, 1152, N_, 1088, nullptr);
        node_attn_kernel<<<6250, 256>>>(src, dst, edge_feat, edge_times, te_w, te_phi, l);
        // agg2 = aggm @ We_v^T
        mma_gemm<false, false><<<dim3(GX, 2), 256, GSMEM_BYTES>>>(
            pAggm3, 256, pWev3 + (size_t)l * 256 * 256, 256,
            nullptr, pAgg2, 256, N_, 256, nullptr);
        node_update_kernel<<<6250, 256>>>(attn_ln_w + l * 256, attn_ln_b + l * 256,
                                          ln_w + l * 256, ln_b + l * 256);
    }

    // out = gelu(h @ out_w^T + out_b)
    mma_gemm<true, false><<<dim3(GX, 1), 256, GSMEM_BYTES>>>(ph3, 768, pWout3, 64, out_b,
                                                             out, 64, N_, 64, nullptr);
}

// round 12
// speedup vs baseline: 1.4279x; 1.2315x over previous
#include <cuda_runtime.h>
#include <cuda_fp16.h>
#include <math.h>
#include <stdint.h>

static constexpr int N_ = 50000;
static constexpr int E_ = 200000;

// ---------------- scratch ----------------
__device__ __half  g_X2   [(size_t)N_ * 512];   // [hi|lo] fp16 split of [nf|mem]
__device__ float   g_h    [(size_t)N_ * 256];
__device__ __half  g_h2   [(size_t)N_ * 512];   // [hi|lo] split of h
__device__ float   g_hkvqp[(size_t)N_ * 1152];  // [K'|V'|Q'|P(320)|pad] (biases folded)
__device__ float   g_agg  [(size_t)N_ * 256];
__device__ float   g_agg2 [(size_t)N_ * 256];
__device__ __half  g_aggm2[(size_t)N_ * 192];   // [hi80|lo80|pad32] fp16 split of aggm
__device__ float   g_nrm  [N_];
__device__ float   g_Wall [2 * 1152 * 256];     // fp32 [Wk;Wv;Wq;Wfused;0]
__device__ __half  g_Wall2[2 * 1152 * 512];     // dup fp16
__device__ float   g_bias1152[2 * 1152];        // [bk|bv|bq_eff|cb|0]
__device__ __half  g_Win2 [256 * 512];
__device__ float   g_Wev  [2 * 256 * 80];
__device__ __half  g_Wev2 [2 * 256 * 192];
__device__ __half  g_Wout2[64 * 512];
__device__ float   g_b    [2 * 768];            // [bk|bv|bq_eff]
// CSR
__device__ int g_off [N_ + 1];
__device__ int g_cnt [N_];
__device__ int g_eid [E_];

// ---------------- ptx helpers (family-safe, sm_80 baseline) ----------------
__device__ __forceinline__ uint32_t smem_u32(const void* p) {
    uint32_t a;
    asm("{ .reg .u64 t; cvta.to.shared.u64 t, %1; cvt.u32.u64 %0, t; }" : "=r"(a) : "l"(p));
    return a;
}
__device__ __forceinline__ void cp16(uint32_t dst, const void* src, int pred) {
    asm volatile(
        "{\n\t.reg .pred p;\n\t"
        "setp.ne.u32 p, %2, 0;\n\t"
        "@p cp.async.ca.shared.global [%0], [%1], 16;\n\t"
        "@!p cp.async.ca.shared.global [%0], [%1], 16, 0;\n\t}"
        :: "r"(dst), "l"(src), "r"(pred) : "memory");
}
__device__ __forceinline__ void cp_commit() {
    asm volatile("cp.async.commit_group;" ::: "memory");
}
__device__ __forceinline__ void ldm4(uint32_t* r, uint32_t addr) {
    asm volatile("ldmatrix.sync.aligned.m8n8.x4.shared.b16 {%0,%1,%2,%3}, [%4];"
                 : "=r"(r[0]), "=r"(r[1]), "=r"(r[2]), "=r"(r[3]) : "r"(addr));
}
__device__ __forceinline__ void ldm2(uint32_t* r, uint32_t addr) {
    asm volatile("ldmatrix.sync.aligned.m8n8.x2.shared.b16 {%0,%1}, [%2];"
                 : "=r"(r[0]), "=r"(r[1]) : "r"(addr));
}
__device__ __forceinline__ void mma16816(float* c, const uint32_t* a, const uint32_t* b) {
    asm volatile(
        "mma.sync.aligned.m16n8k16.row.col.f32.f16.f16.f32 "
        "{%0,%1,%2,%3},{%4,%5,%6,%7},{%8,%9},{%0,%1,%2,%3};"
        : "+f"(c[0]), "+f"(c[1]), "+f"(c[2]), "+f"(c[3])
        : "r"(a[0]), "r"(a[1]), "r"(a[2]), "r"(a[3]), "r"(b[0]), "r"(b[1]));
}

// ---------------- mma.sync GEMM (double-buffered, K chunks of 64) ----------------
static constexpr int GSAS = 72;
static constexpr int GSEG = 128 * GSAS;
static constexpr int GSMEM_BYTES = 4 * GSEG * 2;  // 73728

template <bool GELU, bool SPLIT>
__global__ __launch_bounds__(256)
void mma_gemm(const __half* __restrict__ A2, int ka,
              const __half* __restrict__ W2, int noutW,
              const float* __restrict__ bias,
              float* __restrict__ C, int ldc, int M, int noutC,
              __half* __restrict__ S2) {
    extern __shared__ __align__(16) __half smem[];
    int tid = threadIdx.x, lane = tid & 31, wid = tid >> 5;
    int wm = wid & 1, wn = wid >> 1;
    int bm = blockIdx.x * 128, bn = blockIdx.y * 128;
    int NC = ka >> 6;
    uint32_t sU = smem_u32(smem);

    int arow = (lane & 7) + ((lane >> 3) & 1) * 8;
    int acol = ((lane >> 4) & 1) * 8;
    int brow = lane & 7;
    int bk   = ((lane >> 3) & 1) * 8;

    float acc[4][4][4] = {};

#define LOADC(c, buf)                                                                    \
    {                                                                                    \
        int _c64 = (c) * 64;                                                             \
        uint32_t _ab = sU + (buf) * (2 * GSEG * 2);                                      \
        uint32_t _bb = _ab + GSEG * 2;                                                   \
        _Pragma("unroll")                                                                \
        for (int _k = 0; _k < 4; _k++) {                                                 \
            int _id = tid + _k * 256;                                                    \
            int _r = _id >> 3, _cg = (_id & 7) * 8;                                      \
            uint32_t _so = (uint32_t)(_r * GSAS + _cg) * 2;                              \
            int _gr = bm + _r; int _pa = _gr < M; int _ga = _pa ? _gr : 0;               \
            cp16(_ab + _so, A2 + (size_t)_ga * ka + _c64 + _cg, _pa);                    \
            int _wr = bn + _r; int _pb = _wr < noutW; int _wa = _pb ? _wr : 0;           \
            cp16(_bb + _so, W2 + (size_t)_wa * ka + _c64 + _cg, _pb);                    \
        }                                                                                \
        cp_commit();                                                                     \
    }

    LOADC(0, 0);
    for (int c = 0; c < NC; c++) {
        if (c + 1 < NC) {
            LOADC(c + 1, (c + 1) & 1);
            asm volatile("cp.async.wait_group 1;" ::: "memory");
        } else {
            asm volatile("cp.async.wait_group 0;" ::: "memory");
        }
        __syncthreads();
        uint32_t sAb = sU + (c & 1) * (2 * GSEG * 2);
        uint32_t sBb = sAb + GSEG * 2;
#pragma unroll
        for (int ks = 0; ks < 4; ks++) {
            uint32_t af[4][4];
#pragma unroll
            for (int mf = 0; mf < 4; mf++)
                ldm4(af[mf], sAb + (uint32_t)((wm * 64 + mf * 16 + arow) * GSAS + ks * 16 + acol) * 2);
            uint32_t bf[4][2];
#pragma unroll
            for (int nf = 0; nf < 4; nf++)
                ldm2(bf[nf], sBb + (uint32_t)((wn * 32 + nf * 8 + brow) * GSAS + ks * 16 + bk) * 2);
#pragma unroll
            for (int mf = 0; mf < 4; mf++)
#pragma unroll
                for (int nf = 0; nf < 4; nf++)
                    mma16816(acc[mf][nf], af[mf], bf[nf]);
        }
        __syncthreads();
    }
#undef LOADC

    int cr = lane >> 2, cc = (lane & 3) * 2;
#pragma unroll
    for (int mf = 0; mf < 4; mf++) {
#pragma unroll
        for (int nf = 0; nf < 4; nf++) {
            int col = bn + wn * 32 + nf * 8 + cc;
            if (col >= noutC) continue;
            float bz0 = bias ? bias[col] : 0.f;
            float bz1 = bias ? bias[col + 1] : 0.f;
#pragma unroll
            for (int hh = 0; hh < 2; hh++) {
                int row = bm + wm * 64 + mf * 16 + cr + hh * 8;
                if (row >= M) continue;
                float v0 = acc[mf][nf][hh * 2 + 0] + bz0;
                float v1 = acc[mf][nf][hh * 2 + 1] + bz1;
                if (GELU) {
                    v0 = 0.5f * v0 * (1.0f + erff(v0 * 0.70710678118654752f));
                    v1 = 0.5f * v1 * (1.0f + erff(v1 * 0.70710678118654752f));
                }
                *reinterpret_cast<float2*>(C + (size_t)row * ldc + col) = make_float2(v0, v1);
                if (SPLIT) {
                    size_t b2 = (size_t)row * 2 * noutC;
                    __half h0 = __float2half(v0);
                    __half l0 = __float2half(v0 - __half2float(h0));
                    __half h1 = __float2half(v1);
                    __half l1 = __float2half(v1 - __half2float(h1));
                    S2[b2 + col] = h0; S2[b2 + col + 1] = h1;
                    S2[b2 + noutC + col] = l0; S2[b2 + noutC + col + 1] = l1;
                }
            }
        }
    }
}

// ---------------- pack / conversion ----------------
__global__ void pack_x2_kernel(const float* __restrict__ nf, const float* __restrict__ mem) {
    int idx = blockIdx.x * blockDim.x + threadIdx.x;
    int stride = gridDim.x * blockDim.x;
    for (int i = idx; i < N_ * 256; i += stride) {
        int n = i >> 8, j = i & 255;
        float v = (j < 128) ? nf[n * 128 + j] : mem[n * 128 + (j - 128)];
        __half hi = __float2half(v);
        __half lo = __float2half(v - __half2float(hi));
        size_t b = (size_t)n * 512;
        g_X2[b + j] = hi; g_X2[b + 256 + j] = lo;
    }
}

__global__ void pack_b_kernel(const float* __restrict__ wk_b, const float* __restrict__ wv_b,
                              const float* __restrict__ wq_b, const float* __restrict__ wq_w,
                              const float* __restrict__ te_phi) {
    int idx = blockIdx.x * blockDim.x + threadIdx.x;
    if (idx >= 2 * 768) return;
    int l = idx / 768, r = idx % 768;
    float v;
    if (r < 256)      v = wk_b[l * 256 + r];
    else if (r < 512) v = wv_b[l * 256 + (r - 256)];
    else {
        int rq = r - 512;
        v = wq_b[l * 256 + rq];
        for (int t = 0; t < 16; t++) {
            float ph = te_phi[l * 16 + t];
            float qt = (t == 0) ? ph : sinf(ph);
            v += wq_w[(size_t)(l * 256 + rq) * 272 + 256 + t] * qt;
        }
    }
    g_b[idx] = v;
}

__global__ void pack_wall_base_kernel(const float* __restrict__ wk_w, const float* __restrict__ wv_w,
                                      const float* __restrict__ wq_w) {
    int idx = blockIdx.x * blockDim.x + threadIdx.x;
    int stride = gridDim.x * blockDim.x;
    for (int i = idx; i < 2 * 1152 * 256; i += stride) {
        int l = i / (1152 * 256); int r = (i / 256) % 1152; int k = i & 255;
        if (r < 256)      g_Wall[i] = wk_w[(size_t)(l * 256 + r)       * 336 + k];
        else if (r < 512) g_Wall[i] = wv_w[(size_t)(l * 256 + (r-256)) * 336 + k];
        else if (r < 768) g_Wall[i] = wq_w[(size_t)(l * 256 + (r-512)) * 272 + k];
        else if (r >= 1088) g_Wall[i] = 0.f;
    }
    for (int i = idx; i < 2 * 1152; i += stride) {
        int l = i / 1152, r = i % 1152;
        if (r < 768)       g_bias1152[i] = g_b[l * 768 + r];
        else if (r >= 1088) g_bias1152[i] = 0.f;
    }
    for (int i = idx; i < 2 * 256 * 80; i += stride) {
        int l = i / (256 * 80); int r = (i / 80) % 256; int p = i % 80;
        g_Wev[i] = wv_w[(size_t)(l * 256 + r) * 336 + 256 + p];
    }
}

__global__ __launch_bounds__(256)
void pack_wall_fused_kernel(const float* __restrict__ wk_w, const float* __restrict__ wq_w) {
    __shared__ float wk_s[64];
    int b = blockIdx.x;               // 0..639
    int l = b / 320, q = b % 320;
    int hd = q / 80, p = q % 80;
    int t = threadIdx.x;
    if (t < 64) wk_s[t] = wk_w[(size_t)(l * 256 + 64 * hd + t) * 336 + 256 + p];
    __syncthreads();
    float acc = 0.f;
    for (int c = 0; c < 64; c++)
        acc += wk_s[c] * wq_w[(size_t)(l * 256 + 64 * hd + c) * 272 + t];
    g_Wall[(size_t)l * 1152 * 256 + (size_t)(768 + q) * 256 + t] = acc;
    if (t == 0) {
        float cb = 0.f;
        for (int c = 0; c < 64; c++) cb += wk_s[c] * g_b[l * 768 + 512 + 64 * hd + c];
        g_bias1152[l * 1152 + 768 + q] = cb;
    }
}

// duplicate fp32 weights (rows x K0) -> fp16 [w|w|0pad] (rows x KA)
__global__ void conv_dup_kernel(const float* __restrict__ src, int rows, int K0,
                                __half* __restrict__ dst, int KA) {
    int idx = blockIdx.x * blockDim.x + threadIdx.x;
    int stride = gridDim.x * blockDim.x;
    long total = (long)rows * KA;
    for (long i = idx; i < total; i += stride) {
        int r = (int)(i / KA); int j = (int)(i % KA);
        float v = 0.f;
        if (j < 2 * K0) v = src[(size_t)r * K0 + (j < K0 ? j : j - K0)];
        dst[i] = __float2half(v);
    }
}

// ---------------- CSR build ----------------
__global__ void csr_zero_kernel() {
    int i = blockIdx.x * blockDim.x + threadIdx.x;
    if (i < N_) g_cnt[i] = 0;
}
__global__ void csr_count_kernel(const int* __restrict__ dst) {
    int e = blockIdx.x * blockDim.x + threadIdx.x;
    if (e < E_) atomicAdd(&g_cnt[dst[e]], 1);
}
__global__ __launch_bounds__(1024)
void csr_scan_kernel() {
    __shared__ int sh[1024];
    int tid = threadIdx.x;
    const int CH = (N_ + 1023) / 1024;   // 49
    int lo = tid * CH, hi = min(lo + CH, N_);
    int s = 0;
    for (int i = lo; i < hi; i++) s += g_cnt[i];
    sh[tid] = s;
    __syncthreads();
    for (int ofs = 1; ofs < 1024; ofs <<= 1) {
        int v = (tid >= ofs) ? sh[tid - ofs] : 0;
        __syncthreads();
        sh[tid] += v;
        __syncthreads();
    }
    int run = sh[tid] - s;   // exclusive prefix
    for (int i = lo; i < hi; i++) {
        g_off[i] = run;
        run += g_cnt[i];
        g_cnt[i] = 0;        // reset as fill cursor
    }
    if (tid == 1023) g_off[N_] = sh[1023];
}
__global__ void csr_fill_kernel(const int* __restrict__ dst) {
    int e = blockIdx.x * blockDim.x + threadIdx.x;
    if (e >= E_) return;
    int d = dst[e];
    int pos = atomicAdd(&g_cnt[d], 1);
    g_eid[g_off[d] + pos] = e;
}

// ---------------- node-centric attention (gather, no atomics) ----------------
__global__ __launch_bounds__(256)
void node_attn_kernel(const int* __restrict__ src, const int* __restrict__ dst,
                      const float* __restrict__ ef, const float* __restrict__ et,
                      const float* __restrict__ te_w, const float* __restrict__ te_phi, int l) {
    int d = (blockIdx.x * blockDim.x + threadIdx.x) >> 5;
    int lane = threadIdx.x & 31;
    if (d >= N_) return;
    int jn = dst[d];                       // faithful h_dst[dst] quirk
    size_t jb = (size_t)jn * 1152;
    int o = lane * 8;
    int hl = lane & 7;

    float q[8];
    {
        float4 q0 = *reinterpret_cast<const float4*>(g_hkvqp + jb + 512 + o);
        float4 q1 = *reinterpret_cast<const float4*>(g_hkvqp + jb + 512 + o + 4);
        q[0]=q0.x; q[1]=q0.y; q[2]=q0.z; q[3]=q0.w; q[4]=q1.x; q[5]=q1.y; q[6]=q1.z; q[7]=q1.w;
    }
    float Pv[10];
    {
        const float* Pr = g_hkvqp + jb + 768 + (lane >> 3) * 80 + hl;
#pragma unroll
        for (int t = 0; t < 10; t++) Pv[t] = Pr[8 * t];
    }
    float tw = 0.f, tph = 0.f;
    if (lane < 16) { tw = te_w[l * 16 + lane]; tph = te_phi[l * 16 + lane]; }

    float aggv[8] = {};
    float am0 = 0.f, am1 = 0.f, am2 = 0.f;
    float nrm = 0.f;

    int beg = g_off[d], end = g_off[d + 1];
    for (int ii = beg; ii < end; ii++) {
        int e = g_eid[ii];
        int s = src[e];
        size_t sb = (size_t)s * 1152;
        const float* efp = ef + (size_t)e * 64;

        float tv = 0.f;
        {
            float te = et[e];
            if (lane < 16) {
                float wt = -te * tw + tph;
                tv = (lane == 0) ? wt : sinf(wt);
            }
        }
        float acc = 0.f;
        {
            float4 hk0 = *reinterpret_cast<const float4*>(g_hkvqp + sb + o);
            float4 hk1 = *reinterpret_cast<const float4*>(g_hkvqp + sb + o + 4);
            acc += hk0.x * q[0] + hk0.y * q[1] + hk0.z * q[2] + hk0.w * q[3];
            acc += hk1.x * q[4] + hk1.y * q[5] + hk1.z * q[6] + hk1.w * q[7];
        }
#pragma unroll
        for (int t = 0; t < 8; t++) acc += Pv[t] * efp[hl + 8 * t];
        float t8 = __shfl_sync(0xffffffffu, tv, hl);
        float t9 = __shfl_sync(0xffffffffu, tv, hl + 8);
        acc += Pv[8] * t8 + Pv[9] * t9;

        acc += __shfl_xor_sync(0xffffffffu, acc, 1);
        acc += __shfl_xor_sync(0xffffffffu, acc, 2);
        acc += __shfl_xor_sync(0xffffffffu, acc, 4);
        float sc = fminf(5.0f, fmaxf(-5.0f, acc * 0.125f));
        float a = __expf(sc);
        float sm = a;
        sm += __shfl_xor_sync(0xffffffffu, sm, 8);
        sm += __shfl_xor_sync(0xffffffffu, sm, 16);
        float af = sm * 0.25f;

        {
            float4 hv0 = *reinterpret_cast<const float4*>(g_hkvqp + sb + 256 + o);
            float4 hv1 = *reinterpret_cast<const float4*>(g_hkvqp + sb + 256 + o + 4);
            aggv[0] += hv0.x * af; aggv[1] += hv0.y * af; aggv[2] += hv0.z * af; aggv[3] += hv0.w * af;
            aggv[4] += hv1.x * af; aggv[5] += hv1.y * af; aggv[6] += hv1.z * af; aggv[7] += hv1.w * af;
        }
        am0 += efp[lane] * af;
        am1 += efp[32 + lane] * af;
        if (lane < 16) am2 += tv * af;
        nrm += af;
    }

    size_t base = (size_t)d * 256;
    *reinterpret_cast<float4*>(g_agg + base + o)     = make_float4(aggv[0], aggv[1], aggv[2], aggv[3]);
    *reinterpret_cast<float4*>(g_agg + base + o + 4) = make_float4(aggv[4], aggv[5], aggv[6], aggv[7]);
    if (lane == 0) g_nrm[d] = nrm;

    // aggm2: [hi(80) | lo(80) | pad(32, stays zero)]
    __half* am = g_aggm2 + (size_t)d * 192;
    {
        __half h0 = __float2half(am0);
        __half l0 = __float2half(am0 - __half2float(h0));
        am[lane] = h0; am[80 + lane] = l0;
        __half h1 = __float2half(am1);
        __half l1 = __float2half(am1 - __half2float(h1));
        am[32 + lane] = h1; am[112 + lane] = l1;
        if (lane < 16) {
            __half h2 = __float2half(am2);
            __half l2 = __float2half(am2 - __half2float(h2));
            am[64 + lane] = h2; am[144 + lane] = l2;
        }
    }
}

// ---------------- node update: h = LN(h + LN((agg+agg2)/(nrm+eps))); writes h and h2 ----------------
__global__ __launch_bounds__(256)
void node_update_kernel(const float* __restrict__ aw, const float* __restrict__ ab,
                        const float* __restrict__ lw, const float* __restrict__ lb) {
    int n = (blockIdx.x * blockDim.x + threadIdx.x) >> 5;
    int lane = threadIdx.x & 31;
    if (n >= N_) return;
    size_t base = (size_t)n * 256;
    int o = lane * 8;
    float inv = 1.0f / (g_nrm[n] + 1e-8f);
    float x[8];
    {
        float4 a0 = *reinterpret_cast<const float4*>(g_agg  + base + o);
        float4 a1 = *reinterpret_cast<const float4*>(g_agg  + base + o + 4);
        float4 b0 = *reinterpret_cast<const float4*>(g_agg2 + base + o);
        float4 b1 = *reinterpret_cast<const float4*>(g_agg2 + base + o + 4);
        x[0] = (a0.x + b0.x) * inv; x[1] = (a0.y + b0.y) * inv;
        x[2] = (a0.z + b0.z) * inv; x[3] = (a0.w + b0.w) * inv;
        x[4] = (a1.x + b1.x) * inv; x[5] = (a1.y + b1.y) * inv;
        x[6] = (a1.z + b1.z) * inv; x[7] = (a1.w + b1.w) * inv;
    }
    float s = 0.f;
#pragma unroll
    for (int i = 0; i < 8; i++) s += x[i];
#pragma unroll
    for (int m = 16; m >= 1; m >>= 1) s += __shfl_xor_sync(0xffffffffu, s, m);
    float mean = s * (1.0f / 256.0f);
    float vv = 0.f;
#pragma unroll
    for (int i = 0; i < 8; i++) { float dx = x[i] - mean; vv += dx * dx; }
#pragma unroll
    for (int m = 16; m >= 1; m >>= 1) vv += __shfl_xor_sync(0xffffffffu, vv, m);
    float is = rsqrtf(vv * (1.0f / 256.0f) + 1e-5f);
    float r[8];
#pragma unroll
    for (int i = 0; i < 8; i++) {
        float hn = (x[i] - mean) * is * aw[o + i] + ab[o + i];
        r[i] = g_h[base + o + i] + hn;
    }
    float s2 = 0.f;
#pragma unroll
    for (int i = 0; i < 8; i++) s2 += r[i];
#pragma unroll
    for (int m = 16; m >= 1; m >>= 1) s2 += __shfl_xor_sync(0xffffffffu, s2, m);
    float mean2 = s2 * (1.0f / 256.0f);
    float v2 = 0.f;
#pragma unroll
    for (int i = 0; i < 8; i++) { float dx = r[i] - mean2; v2 += dx * dx; }
#pragma unroll
    for (int m = 16; m >= 1; m >>= 1) v2 += __shfl_xor_sync(0xffffffffu, v2, m);
    float is2 = rsqrtf(v2 * (1.0f / 256.0f) + 1e-5f);
    size_t b2 = (size_t)n * 512;
#pragma unroll
    for (int i = 0; i < 8; i++) {
        float hv = (r[i] - mean2) * is2 * lw[o + i] + lb[o + i];
        g_h[base + o + i] = hv;
        __half hi = __float2half(hv);
        __half lo = __float2half(hv - __half2float(hi));
        g_h2[b2 + o + i] = hi;
        g_h2[b2 + 256 + o + i] = lo;
    }
}

// ---------------- launch ----------------
extern "C" void kernel_launch(void* const* d_in, const int* in_sizes, int n_in,
                              void* d_out, int out_size) {
    const float* node_feat  = (const float*)d_in[0];
    const float* memory     = (const float*)d_in[1];
    const int*   eidx       = (const int*)  d_in[2];
    const float* edge_feat  = (const float*)d_in[3];
    const float* edge_times = (const float*)d_in[4];
    const float* in_w       = (const float*)d_in[5];
    const float* in_b       = (const float*)d_in[6];
    const float* te_w       = (const float*)d_in[7];
    const float* te_phi     = (const float*)d_in[8];
    const float* wq_w       = (const float*)d_in[9];
    const float* wq_b       = (const float*)d_in[10];
    const float* wk_w       = (const float*)d_in[11];
    const float* wk_b       = (const float*)d_in[12];
    const float* wv_w       = (const float*)d_in[13];
    const float* wv_b       = (const float*)d_in[14];
    const float* attn_ln_w  = (const float*)d_in[15];
    const float* attn_ln_b  = (const float*)d_in[16];
    const float* ln_w       = (const float*)d_in[17];
    const float* ln_b       = (const float*)d_in[18];
    const float* out_w      = (const float*)d_in[19];
    const float* out_b      = (const float*)d_in[20];
    const int* src = eidx;
    const int* dst = eidx + E_;
    float* out = (float*)d_out;

    float *ph, *phkvqp, *pAgg2, *pWall, *pWev, *pBias;
    __half *pX2, *ph2, *pAggm2, *pWall2, *pWin2, *pWev2, *pWout2;
    cudaGetSymbolAddress((void**)&ph,     g_h);
    cudaGetSymbolAddress((void**)&phkvqp, g_hkvqp);
    cudaGetSymbolAddress((void**)&pAgg2,  g_agg2);
    cudaGetSymbolAddress((void**)&pWall,  g_Wall);
    cudaGetSymbolAddress((void**)&pWev,   g_Wev);
    cudaGetSymbolAddress((void**)&pBias,  g_bias1152);
    cudaGetSymbolAddress((void**)&pX2,    g_X2);
    cudaGetSymbolAddress((void**)&ph2,    g_h2);
    cudaGetSymbolAddress((void**)&pAggm2, g_aggm2);
    cudaGetSymbolAddress((void**)&pWall2, g_Wall2);
    cudaGetSymbolAddress((void**)&pWin2,  g_Win2);
    cudaGetSymbolAddress((void**)&pWev2,  g_Wev2);
    cudaGetSymbolAddress((void**)&pWout2, g_Wout2);

    cudaFuncSetAttribute(mma_gemm<false, true>,  cudaFuncAttributeMaxDynamicSharedMemorySize, GSMEM_BYTES);
    cudaFuncSetAttribute(mma_gemm<false, false>, cudaFuncAttributeMaxDynamicSharedMemorySize, GSMEM_BYTES);
    cudaFuncSetAttribute(mma_gemm<true, false>,  cudaFuncAttributeMaxDynamicSharedMemorySize, GSMEM_BYTES);

    const int GX = (N_ + 127) / 128;  // 391

    pack_x2_kernel<<<4096, 256>>>(node_feat, memory);
    pack_b_kernel<<<6, 256>>>(wk_b, wv_b, wq_b, wq_w, te_phi);
    pack_wall_base_kernel<<<2304, 256>>>(wk_w, wv_w, wq_w);
    pack_wall_fused_kernel<<<640, 256>>>(wk_w, wq_w);
    conv_dup_kernel<<<4096, 256>>>(pWall, 2 * 1152, 256, pWall2, 512);
    conv_dup_kernel<<<512, 256>>>((const float*)in_w, 256, 256, pWin2, 512);
    conv_dup_kernel<<<128, 256>>>((const float*)out_w, 64, 256, pWout2, 512);
    conv_dup_kernel<<<384, 256>>>(pWev, 2 * 256, 80, pWev2, 192);

    // CSR build (topology is layer-independent)
    csr_zero_kernel<<<(N_ + 255) / 256, 256>>>();
    csr_count_kernel<<<(E_ + 255) / 256, 256>>>(dst);
    csr_scan_kernel<<<1, 1024>>>();
    csr_fill_kernel<<<(E_ + 255) / 256, 256>>>(dst);

    // h = X @ in_w^T + in_b (also emits h2 split)
    mma_gemm<false, true><<<dim3(GX, 2), 256, GSMEM_BYTES>>>(pX2, 512, pWin2, 256, in_b,
                                                             ph, 256, N_, 256, ph2);

    for (int l = 0; l < 2; l++) {
        // [K'|V'|Q'|P] = h @ W_all^T + [bk|bv|bq_eff|cb]
        mma_gemm<false, false><<<dim3(GX, 9), 256, GSMEM_BYTES>>>(
            ph2, 512, pWall2 + (size_t)l * 1152 * 512, 1152,
            pBias + l * 1152, phkvqp, 1152, N_, 1088, nullptr);
        node_attn_kernel<<<6250, 256>>>(src, dst, edge_feat, edge_times, te_w, te_phi, l);
        // agg2 = aggm @ We_v^T
        mma_gemm<false, false><<<dim3(GX, 2), 256, GSMEM_BYTES>>>(
            pAggm2, 192, pWev2 + (size_t)l * 256 * 192, 256,
            nullptr, pAgg2, 256, N_, 256, nullptr);
        node_update_kernel<<<6250, 256>>>(attn_ln_w + l * 256, attn_ln_b + l * 256,
                                          ln_w + l * 256, ln_b + l * 256);
    }

    // out = gelu(h @ out_w^T + out_b)
    mma_gemm<true, false><<<dim3(GX, 1), 256, GSMEM_BYTES>>>(ph2, 512, pWout2, 64, out_b,
                                                             out, 64, N_, 64, nullptr);
}

// round 13
// speedup vs baseline: 1.4519x; 1.0168x over previous
#include <cuda_runtime.h>
#include <cuda_fp16.h>
#include <math.h>
#include <stdint.h>

static constexpr int N_ = 50000;
static constexpr int E_ = 200000;

// ---------------- scratch ----------------
__device__ __half  g_X2   [(size_t)N_ * 512];   // [hi|lo] fp16 split of [nf|mem]
__device__ float   g_h    [(size_t)N_ * 256];
__device__ __half  g_h2   [(size_t)N_ * 512];   // [hi|lo] split of h
__device__ float   g_hkvqp[(size_t)N_ * 1152];  // [K'(256)|Q'(256)|P(320)|V'(256)|pad]
__device__ float   g_agg  [(size_t)N_ * 256];
__device__ float   g_agg2 [(size_t)N_ * 256];
__device__ __half  g_aggm2[(size_t)N_ * 192];   // [hi80|lo80|pad32] fp16 split of aggm
__device__ float   g_nrm  [N_];
__device__ float   g_Wall [2 * 1152 * 256];     // fp32 [Wk;Wv;Wq;Wfused]
__device__ __half  g_Wkqp2[2 * 832 * 512];      // dup fp16 [Wk;Wq;Wfused]
__device__ __half  g_Wv2h [2 * 256 * 256];      // single fp16 Wv
__device__ float   g_bias_kqp[2 * 832];         // [bk|bq_eff|cb]
__device__ float   g_bias_v  [2 * 256];         // bv
__device__ __half  g_Win2 [256 * 512];
__device__ float   g_Wev  [2 * 256 * 80];
__device__ __half  g_Wev2 [2 * 256 * 192];
__device__ __half  g_Wout2[64 * 512];
__device__ float   g_b    [2 * 768];            // [bk|bv|bq_eff]
// CSR
__device__ int g_off [N_ + 1];
__device__ int g_cnt [N_];
__device__ int g_eid [E_];

// ---------------- ptx helpers (family-safe, sm_80 baseline) ----------------
__device__ __forceinline__ uint32_t smem_u32(const void* p) {
    uint32_t a;
    asm("{ .reg .u64 t; cvta.to.shared.u64 t, %1; cvt.u32.u64 %0, t; }" : "=r"(a) : "l"(p));
    return a;
}
__device__ __forceinline__ void cp16(uint32_t dst, const void* src, int pred) {
    asm volatile(
        "{\n\t.reg .pred p;\n\t"
        "setp.ne.u32 p, %2, 0;\n\t"
        "@p cp.async.ca.shared.global [%0], [%1], 16;\n\t"
        "@!p cp.async.ca.shared.global [%0], [%1], 16, 0;\n\t}"
        :: "r"(dst), "l"(src), "r"(pred) : "memory");
}
__device__ __forceinline__ void cp_commit() {
    asm volatile("cp.async.commit_group;" ::: "memory");
}
__device__ __forceinline__ void ldm4(uint32_t* r, uint32_t addr) {
    asm volatile("ldmatrix.sync.aligned.m8n8.x4.shared.b16 {%0,%1,%2,%3}, [%4];"
                 : "=r"(r[0]), "=r"(r[1]), "=r"(r[2]), "=r"(r[3]) : "r"(addr));
}
__device__ __forceinline__ void mma16816(float* c, const uint32_t* a, const uint32_t* b) {
    asm volatile(
        "mma.sync.aligned.m16n8k16.row.col.f32.f16.f16.f32 "
        "{%0,%1,%2,%3},{%4,%5,%6,%7},{%8,%9},{%0,%1,%2,%3};"
        : "+f"(c[0]), "+f"(c[1]), "+f"(c[2]), "+f"(c[3])
        : "r"(a[0]), "r"(a[1]), "r"(a[2]), "r"(a[3]), "r"(b[0]), "r"(b[1]));
}

// ---------------- mma.sync GEMM (double-buffered, K chunks of 64) ----------------
static constexpr int GSAS = 72;
static constexpr int GSEG = 128 * GSAS;
static constexpr int GSMEM_BYTES = 4 * GSEG * 2;  // 73728

template <bool GELU, bool SPLIT>
__global__ __launch_bounds__(256)
void mma_gemm(const __half* __restrict__ A2, int lda, int klen,
              const __half* __restrict__ W2, int ldw, int noutW,
              const float* __restrict__ bias,
              float* __restrict__ C, int ldc, int M, int noutC,
              __half* __restrict__ S2) {
    extern __shared__ __align__(16) __half smem[];
    int tid = threadIdx.x, lane = tid & 31, wid = tid >> 5;
    int wm = wid & 1, wn = wid >> 1;
    int bm = blockIdx.x * 128, bn = blockIdx.y * 128;
    int NC = klen >> 6;
    uint32_t sU = smem_u32(smem);

    int arow = (lane & 7) + ((lane >> 3) & 1) * 8;
    int acol = ((lane >> 4) & 1) * 8;
    int bco  = ((lane >> 4) & 1) * 8 + (lane & 7);  // col offset within nf-pair block
    int bko  = ((lane >> 3) & 1) * 8;               // k-half offset

    float acc[4][4][4] = {};

#define LOADC(c, buf)                                                                    \
    {                                                                                    \
        int _c64 = (c) * 64;                                                             \
        uint32_t _ab = sU + (buf) * (2 * GSEG * 2);                                      \
        uint32_t _bb = _ab + GSEG * 2;                                                   \
        _Pragma("unroll")                                                                \
        for (int _k = 0; _k < 4; _k++) {                                                 \
            int _id = tid + _k * 256;                                                    \
            int _r = _id >> 3, _cg = (_id & 7) * 8;                                      \
            uint32_t _so = (uint32_t)(_r * GSAS + _cg) * 2;                              \
            int _gr = bm + _r; int _pa = _gr < M; int _ga = _pa ? _gr : 0;               \
            cp16(_ab + _so, A2 + (size_t)_ga * lda + _c64 + _cg, _pa);                   \
            int _wr = bn + _r; int _pb = _wr < noutW; int _wa = _pb ? _wr : 0;           \
            cp16(_bb + _so, W2 + (size_t)_wa * ldw + _c64 + _cg, _pb);                   \
        }                                                                                \
        cp_commit();                                                                     \
    }

    LOADC(0, 0);
    for (int c = 0; c < NC; c++) {
        if (c + 1 < NC) {
            LOADC(c + 1, (c + 1) & 1);
            asm volatile("cp.async.wait_group 1;" ::: "memory");
        } else {
            asm volatile("cp.async.wait_group 0;" ::: "memory");
        }
        __syncthreads();
        uint32_t sAb = sU + (c & 1) * (2 * GSEG * 2);
        uint32_t sBb = sAb + GSEG * 2;
#pragma unroll
        for (int ks = 0; ks < 4; ks++) {
            uint32_t af[4][4];
#pragma unroll
            for (int mf = 0; mf < 4; mf++)
                ldm4(af[mf], sAb + (uint32_t)((wm * 64 + mf * 16 + arow) * GSAS + ks * 16 + acol) * 2);
            uint32_t bf[4][2];
#pragma unroll
            for (int p = 0; p < 2; p++) {
                uint32_t r4[4];
                ldm4(r4, sBb + (uint32_t)((wn * 32 + p * 16 + bco) * GSAS + ks * 16 + bko) * 2);
                bf[2 * p][0] = r4[0]; bf[2 * p][1] = r4[1];
                bf[2 * p + 1][0] = r4[2]; bf[2 * p + 1][1] = r4[3];
            }
#pragma unroll
            for (int mf = 0; mf < 4; mf++)
#pragma unroll
                for (int nf = 0; nf < 4; nf++)
                    mma16816(acc[mf][nf], af[mf], bf[nf]);
        }
        __syncthreads();
    }
#undef LOADC

    int cr = lane >> 2, cc = (lane & 3) * 2;
#pragma unroll
    for (int mf = 0; mf < 4; mf++) {
#pragma unroll
        for (int nf = 0; nf < 4; nf++) {
            int col = bn + wn * 32 + nf * 8 + cc;
            if (col >= noutC) continue;
            float bz0 = bias ? bias[col] : 0.f;
            float bz1 = bias ? bias[col + 1] : 0.f;
#pragma unroll
            for (int hh = 0; hh < 2; hh++) {
                int row = bm + wm * 64 + mf * 16 + cr + hh * 8;
                if (row >= M) continue;
                float v0 = acc[mf][nf][hh * 2 + 0] + bz0;
                float v1 = acc[mf][nf][hh * 2 + 1] + bz1;
                if (GELU) {
                    v0 = 0.5f * v0 * (1.0f + erff(v0 * 0.70710678118654752f));
                    v1 = 0.5f * v1 * (1.0f + erff(v1 * 0.70710678118654752f));
                }
                *reinterpret_cast<float2*>(C + (size_t)row * ldc + col) = make_float2(v0, v1);
                if (SPLIT) {
                    size_t b2 = (size_t)row * 2 * noutC;
                    __half h0 = __float2half(v0);
                    __half l0 = __float2half(v0 - __half2float(h0));
                    __half h1 = __float2half(v1);
                    __half l1 = __float2half(v1 - __half2float(h1));
                    S2[b2 + col] = h0; S2[b2 + col + 1] = h1;
                    S2[b2 + noutC + col] = l0; S2[b2 + noutC + col + 1] = l1;
                }
            }
        }
    }
}

// ---------------- pack / conversion ----------------
__global__ void pack_x2_kernel(const float* __restrict__ nf, const float* __restrict__ mem) {
    int idx = blockIdx.x * blockDim.x + threadIdx.x;
    int stride = gridDim.x * blockDim.x;
    for (int i = idx; i < N_ * 256; i += stride) {
        int n = i >> 8, j = i & 255;
        float v = (j < 128) ? nf[n * 128 + j] : mem[n * 128 + (j - 128)];
        __half hi = __float2half(v);
        __half lo = __float2half(v - __half2float(hi));
        size_t b = (size_t)n * 512;
        g_X2[b + j] = hi; g_X2[b + 256 + j] = lo;
    }
}

__global__ void pack_b_kernel(const float* __restrict__ wk_b, const float* __restrict__ wv_b,
                              const float* __restrict__ wq_b, const float* __restrict__ wq_w,
                              const float* __restrict__ te_phi) {
    int idx = blockIdx.x * blockDim.x + threadIdx.x;
    if (idx >= 2 * 768) return;
    int l = idx / 768, r = idx % 768;
    float v;
    if (r < 256)      v = wk_b[l * 256 + r];
    else if (r < 512) v = wv_b[l * 256 + (r - 256)];
    else {
        int rq = r - 512;
        v = wq_b[l * 256 + rq];
        for (int t = 0; t < 16; t++) {
            float ph = te_phi[l * 16 + t];
            float qt = (t == 0) ? ph : sinf(ph);
            v += wq_w[(size_t)(l * 256 + rq) * 272 + 256 + t] * qt;
        }
    }
    g_b[idx] = v;
}

__global__ void pack_wall_base_kernel(const float* __restrict__ wk_w, const float* __restrict__ wv_w,
                                      const float* __restrict__ wq_w) {
    int idx = blockIdx.x * blockDim.x + threadIdx.x;
    int stride = gridDim.x * blockDim.x;
    for (int i = idx; i < 2 * 1088 * 256; i += stride) {
        int l = i / (1088 * 256); int r = (i / 256) % 1088; int k = i & 255;
        size_t o = (size_t)l * 1152 * 256 + (size_t)r * 256 + k;
        if (r < 256)      g_Wall[o] = wk_w[(size_t)(l * 256 + r)       * 336 + k];
        else if (r < 512) g_Wall[o] = wv_w[(size_t)(l * 256 + (r-256)) * 336 + k];
        else if (r < 768) g_Wall[o] = wq_w[(size_t)(l * 256 + (r-512)) * 272 + k];
        // 768..1087 filled by fused kernel
    }
    for (int i = idx; i < 2 * 256 * 80; i += stride) {
        int l = i / (256 * 80); int r = (i / 80) % 256; int p = i % 80;
        g_Wev[i] = wv_w[(size_t)(l * 256 + r) * 336 + 256 + p];
    }
}

// rows 768..1087 of W_all: (WeTk blockdiag) @ Wq_h; cb bias into bias_kqp[512..832)
__global__ __launch_bounds__(256)
void pack_wall_fused_kernel(const float* __restrict__ wk_w, const float* __restrict__ wq_w) {
    __shared__ float wk_s[64];
    int b = blockIdx.x;               // 0..639
    int l = b / 320, q = b % 320;
    int hd = q / 80, p = q % 80;
    int t = threadIdx.x;
    if (t < 64) wk_s[t] = wk_w[(size_t)(l * 256 + 64 * hd + t) * 336 + 256 + p];
    __syncthreads();
    float acc = 0.f;
    for (int c = 0; c < 64; c++)
        acc += wk_s[c] * wq_w[(size_t)(l * 256 + 64 * hd + c) * 272 + t];
    g_Wall[(size_t)l * 1152 * 256 + (size_t)(768 + q) * 256 + t] = acc;
    if (t == 0) {
        float cb = 0.f;
        for (int c = 0; c < 64; c++) cb += wk_s[c] * g_b[l * 768 + 512 + 64 * hd + c];
        g_bias_kqp[l * 832 + 512 + q] = cb;
    }
}

// bias_kqp[0..512) = [bk|bq_eff], bias_v = bv
__global__ void pack_bias_split_kernel() {
    int idx = blockIdx.x * blockDim.x + threadIdx.x;
    if (idx < 2 * 512) {
        int l = idx / 512, r = idx % 512;
        g_bias_kqp[l * 832 + r] = (r < 256) ? g_b[l * 768 + r] : g_b[l * 768 + 512 + (r - 256)];
    }
    if (idx < 2 * 256) {
        int l = idx / 256, r = idx % 256;
        g_bias_v[idx] = g_b[l * 768 + 256 + r];
    }
}

// W_kqp fp16 dup: row r<256 -> Wall row r (Wk); 256..832 -> Wall row r+256 (Wq, Wfused)
__global__ void conv_kqp_kernel() {
    int idx = blockIdx.x * blockDim.x + threadIdx.x;
    int stride = gridDim.x * blockDim.x;
    for (int i = idx; i < 2 * 832 * 512; i += stride) {
        int l = i / (832 * 512); int rem = i % (832 * 512);
        int r = rem / 512, j = rem % 512;
        int srcr = (r < 256) ? r : r + 256;
        float v = g_Wall[(size_t)l * 1152 * 256 + (size_t)srcr * 256 + (j < 256 ? j : j - 256)];
        g_Wkqp2[i] = __float2half(v);
    }
}

// Wv single fp16 (256x256)
__global__ void conv_v_kernel() {
    int idx = blockIdx.x * blockDim.x + threadIdx.x;
    int stride = gridDim.x * blockDim.x;
    for (int i = idx; i < 2 * 256 * 256; i += stride) {
        int l = i / (256 * 256); int rem = i % (256 * 256);
        int r = rem / 256, j = rem % 256;
        g_Wv2h[i] = __float2half(g_Wall[(size_t)l * 1152 * 256 + (size_t)(256 + r) * 256 + j]);
    }
}

// duplicate fp32 weights (rows x K0) -> fp16 [w|w|0pad] (rows x KA)
__global__ void conv_dup_kernel(const float* __restrict__ src, int rows, int K0,
                                __half* __restrict__ dst, int KA) {
    int idx = blockIdx.x * blockDim.x + threadIdx.x;
    int stride = gridDim.x * blockDim.x;
    long total = (long)rows * KA;
    for (long i = idx; i < total; i += stride) {
        int r = (int)(i / KA); int j = (int)(i % KA);
        float v = 0.f;
        if (j < 2 * K0) v = src[(size_t)r * K0 + (j < K0 ? j : j - K0)];
        dst[i] = __float2half(v);
    }
}

// ---------------- CSR build ----------------
__global__ void csr_zero_kernel() {
    int i = blockIdx.x * blockDim.x + threadIdx.x;
    if (i < N_) g_cnt[i] = 0;
}
__global__ void csr_count_kernel(const int* __restrict__ dst) {
    int e = blockIdx.x * blockDim.x + threadIdx.x;
    if (e < E_) atomicAdd(&g_cnt[dst[e]], 1);
}
__global__ __launch_bounds__(1024)
void csr_scan_kernel() {
    __shared__ int sh[1024];
    int tid = threadIdx.x;
    const int CH = (N_ + 1023) / 1024;   // 49
    int lo = tid * CH, hi = min(lo + CH, N_);
    int s = 0;
    for (int i = lo; i < hi; i++) s += g_cnt[i];
    sh[tid] = s;
    __syncthreads();
    for (int ofs = 1; ofs < 1024; ofs <<= 1) {
        int v = (tid >= ofs) ? sh[tid - ofs] : 0;
        __syncthreads();
        sh[tid] += v;
        __syncthreads();
    }
    int run = sh[tid] - s;   // exclusive prefix
    for (int i = lo; i < hi; i++) {
        g_off[i] = run;
        run += g_cnt[i];
        g_cnt[i] = 0;        // reset as fill cursor
    }
    if (tid == 1023) g_off[N_] = sh[1023];
}
__global__ void csr_fill_kernel(const int* __restrict__ dst) {
    int e = blockIdx.x * blockDim.x + threadIdx.x;
    if (e >= E_) return;
    int d = dst[e];
    int pos = atomicAdd(&g_cnt[d], 1);
    g_eid[g_off[d] + pos] = e;
}

// ---------------- node-centric attention (gather, no atomics) ----------------
// hkvqp layout: K' at +0, Q' at +256, P at +512, V' at +832
__global__ __launch_bounds__(256)
void node_attn_kernel(const int* __restrict__ src, const int* __restrict__ dst,
                      const float* __restrict__ ef, const float* __restrict__ et,
                      const float* __restrict__ te_w, const float* __restrict__ te_phi, int l) {
    int d = (blockIdx.x * blockDim.x + threadIdx.x) >> 5;
    int lane = threadIdx.x & 31;
    if (d >= N_) return;
    int jn = dst[d];                       // faithful h_dst[dst] quirk
    size_t jb = (size_t)jn * 1152;
    int o = lane * 8;
    int hl = lane & 7;

    float q[8];
    {
        float4 q0 = *reinterpret_cast<const float4*>(g_hkvqp + jb + 256 + o);
        float4 q1 = *reinterpret_cast<const float4*>(g_hkvqp + jb + 256 + o + 4);
        q[0]=q0.x; q[1]=q0.y; q[2]=q0.z; q[3]=q0.w; q[4]=q1.x; q[5]=q1.y; q[6]=q1.z; q[7]=q1.w;
    }
    float Pv[10];
    {
        const float* Pr = g_hkvqp + jb + 512 + (lane >> 3) * 80 + hl;
#pragma unroll
        for (int t = 0; t < 10; t++) Pv[t] = Pr[8 * t];
    }
    float tw = 0.f, tph = 0.f;
    if (lane < 16) { tw = te_w[l * 16 + lane]; tph = te_phi[l * 16 + lane]; }

    float aggv[8] = {};
    float am0 = 0.f, am1 = 0.f, am2 = 0.f;
    float nrm = 0.f;

    int beg = g_off[d], end = g_off[d + 1];
    for (int ii = beg; ii < end; ii++) {
        int e = g_eid[ii];
        int s = src[e];
        size_t sb = (size_t)s * 1152;
        const float* efp = ef + (size_t)e * 64;

        float tv = 0.f;
        {
            float te = et[e];
            if (lane < 16) {
                float wt = -te * tw + tph;
                tv = (lane == 0) ? wt : sinf(wt);
            }
        }
        float acc = 0.f;
        {
            float4 hk0 = *reinterpret_cast<const float4*>(g_hkvqp + sb + o);
            float4 hk1 = *reinterpret_cast<const float4*>(g_hkvqp + sb + o + 4);
            acc += hk0.x * q[0] + hk0.y * q[1] + hk0.z * q[2] + hk0.w * q[3];
            acc += hk1.x * q[4] + hk1.y * q[5] + hk1.z * q[6] + hk1.w * q[7];
        }
#pragma unroll
        for (int t = 0; t < 8; t++) acc += Pv[t] * efp[hl + 8 * t];
        float t8 = __shfl_sync(0xffffffffu, tv, hl);
        float t9 = __shfl_sync(0xffffffffu, tv, hl + 8);
        acc += Pv[8] * t8 + Pv[9] * t9;

        acc += __shfl_xor_sync(0xffffffffu, acc, 1);
        acc += __shfl_xor_sync(0xffffffffu, acc, 2);
        acc += __shfl_xor_sync(0xffffffffu, acc, 4);
        float sc = fminf(5.0f, fmaxf(-5.0f, acc * 0.125f));
        float a = __expf(sc);
        float sm = a;
        sm += __shfl_xor_sync(0xffffffffu, sm, 8);
        sm += __shfl_xor_sync(0xffffffffu, sm, 16);
        float af = sm * 0.25f;

        {
            float4 hv0 = *reinterpret_cast<const float4*>(g_hkvqp + sb + 832 + o);
            float4 hv1 = *reinterpret_cast<const float4*>(g_hkvqp + sb + 832 + o + 4);
            aggv[0] += hv0.x * af; aggv[1] += hv0.y * af; aggv[2] += hv0.z * af; aggv[3] += hv0.w * af;
            aggv[4] += hv1.x * af; aggv[5] += hv1.y * af; aggv[6] += hv1.z * af; aggv[7] += hv1.w * af;
        }
        am0 += efp[lane] * af;
        am1 += efp[32 + lane] * af;
        if (lane < 16) am2 += tv * af;
        nrm += af;
    }

    size_t base = (size_t)d * 256;
    *reinterpret_cast<float4*>(g_agg + base + o)     = make_float4(aggv[0], aggv[1], aggv[2], aggv[3]);
    *reinterpret_cast<float4*>(g_agg + base + o + 4) = make_float4(aggv[4], aggv[5], aggv[6], aggv[7]);
    if (lane == 0) g_nrm[d] = nrm;

    // aggm2: [hi(80) | lo(80) | pad(32, stays zero)]
    __half* am = g_aggm2 + (size_t)d * 192;
    {
        __half h0 = __float2half(am0);
        __half l0 = __float2half(am0 - __half2float(h0));
        am[lane] = h0; am[80 + lane] = l0;
        __half h1 = __float2half(am1);
        __half l1 = __float2half(am1 - __half2float(h1));
        am[32 + lane] = h1; am[112 + lane] = l1;
        if (lane < 16) {
            __half h2 = __float2half(am2);
            __half l2 = __float2half(am2 - __half2float(h2));
            am[64 + lane] = h2; am[144 + lane] = l2;
        }
    }
}

// ---------------- node update: h = LN(h + LN((agg+agg2)/(nrm+eps))); writes h and h2 ----------------
__global__ __launch_bounds__(256)
void node_update_kernel(const float* __restrict__ aw, const float* __restrict__ ab,
                        const float* __restrict__ lw, const float* __restrict__ lb) {
    int n = (blockIdx.x * blockDim.x + threadIdx.x) >> 5;
    int lane = threadIdx.x & 31;
    if (n >= N_) return;
    size_t base = (size_t)n * 256;
    int o = lane * 8;
    float inv = 1.0f / (g_nrm[n] + 1e-8f);
    float x[8];
    {
        float4 a0 = *reinterpret_cast<const float4*>(g_agg  + base + o);
        float4 a1 = *reinterpret_cast<const float4*>(g_agg  + base + o + 4);
        float4 b0 = *reinterpret_cast<const float4*>(g_agg2 + base + o);
        float4 b1 = *reinterpret_cast<const float4*>(g_agg2 + base + o + 4);
        x[0] = (a0.x + b0.x) * inv; x[1] = (a0.y + b0.y) * inv;
        x[2] = (a0.z + b0.z) * inv; x[3] = (a0.w + b0.w) * inv;
        x[4] = (a1.x + b1.x) * inv; x[5] = (a1.y + b1.y) * inv;
        x[6] = (a1.z + b1.z) * inv; x[7] = (a1.w + b1.w) * inv;
    }
    float s = 0.f;
#pragma unroll
    for (int i = 0; i < 8; i++) s += x[i];
#pragma unroll
    for (int m = 16; m >= 1; m >>= 1) s += __shfl_xor_sync(0xffffffffu, s, m);
    float mean = s * (1.0f / 256.0f);
    float vv = 0.f;
#pragma unroll
    for (int i = 0; i < 8; i++) { float dx = x[i] - mean; vv += dx * dx; }
#pragma unroll
    for (int m = 16; m >= 1; m >>= 1) vv += __shfl_xor_sync(0xffffffffu, vv, m);
    float is = rsqrtf(vv * (1.0f / 256.0f) + 1e-5f);
    float r[8];
#pragma unroll
    for (int i = 0; i < 8; i++) {
        float hn = (x[i] - mean) * is * aw[o + i] + ab[o + i];
        r[i] = g_h[base + o + i] + hn;
    }
    float s2 = 0.f;
#pragma unroll
    for (int i = 0; i < 8; i++) s2 += r[i];
#pragma unroll
    for (int m = 16; m >= 1; m >>= 1) s2 += __shfl_xor_sync(0xffffffffu, s2, m);
    float mean2 = s2 * (1.0f / 256.0f);
    float v2 = 0.f;
#pragma unroll
    for (int i = 0; i < 8; i++) { float dx = r[i] - mean2; v2 += dx * dx; }
#pragma unroll
    for (int m = 16; m >= 1; m >>= 1) v2 += __shfl_xor_sync(0xffffffffu, v2, m);
    float is2 = rsqrtf(v2 * (1.0f / 256.0f) + 1e-5f);
    size_t b2 = (size_t)n * 512;
#pragma unroll
    for (int i = 0; i < 8; i++) {
        float hv = (r[i] - mean2) * is2 * lw[o + i] + lb[o + i];
        g_h[base + o + i] = hv;
        __half hi = __float2half(hv);
        __half lo = __float2half(hv - __half2float(hi));
        g_h2[b2 + o + i] = hi;
        g_h2[b2 + 256 + o + i] = lo;
    }
}

// ---------------- launch ----------------
extern "C" void kernel_launch(void* const* d_in, const int* in_sizes, int n_in,
                              void* d_out, int out_size) {
    const float* node_feat  = (const float*)d_in[0];
    const float* memory     = (const float*)d_in[1];
    const int*   eidx       = (const int*)  d_in[2];
    const float* edge_feat  = (const float*)d_in[3];
    const float* edge_times = (const float*)d_in[4];
    const float* in_w       = (const float*)d_in[5];
    const float* in_b       = (const float*)d_in[6];
    const float* te_w       = (const float*)d_in[7];
    const float* te_phi     = (const float*)d_in[8];
    const float* wq_w       = (const float*)d_in[9];
    const float* wq_b       = (const float*)d_in[10];
    const float* wk_w       = (const float*)d_in[11];
    const float* wk_b       = (const float*)d_in[12];
    const float* wv_w       = (const float*)d_in[13];
    const float* wv_b       = (const float*)d_in[14];
    const float* attn_ln_w  = (const float*)d_in[15];
    const float* attn_ln_b  = (const float*)d_in[16];
    const float* ln_w       = (const float*)d_in[17];
    const float* ln_b       = (const float*)d_in[18];
    const float* out_w      = (const float*)d_in[19];
    const float* out_b      = (const float*)d_in[20];
    const int* src = eidx;
    const int* dst = eidx + E_;
    float* out = (float*)d_out;

    float *ph, *phkvqp, *pAgg2, *pWev, *pBiasKQP, *pBiasV;
    __half *pX2, *ph2, *pAggm2, *pWkqp2, *pWv2h, *pWin2, *pWev2, *pWout2;
    cudaGetSymbolAddress((void**)&ph,       g_h);
    cudaGetSymbolAddress((void**)&phkvqp,   g_hkvqp);
    cudaGetSymbolAddress((void**)&pAgg2,    g_agg2);
    cudaGetSymbolAddress((void**)&pWev,     g_Wev);
    cudaGetSymbolAddress((void**)&pBiasKQP, g_bias_kqp);
    cudaGetSymbolAddress((void**)&pBiasV,   g_bias_v);
    cudaGetSymbolAddress((void**)&pX2,      g_X2);
    cudaGetSymbolAddress((void**)&ph2,      g_h2);
    cudaGetSymbolAddress((void**)&pAggm2,   g_aggm2);
    cudaGetSymbolAddress((void**)&pWkqp2,   g_Wkqp2);
    cudaGetSymbolAddress((void**)&pWv2h,    g_Wv2h);
    cudaGetSymbolAddress((void**)&pWin2,    g_Win2);
    cudaGetSymbolAddress((void**)&pWev2,    g_Wev2);
    cudaGetSymbolAddress((void**)&pWout2,   g_Wout2);

    cudaFuncSetAttribute(mma_gemm<false, true>,  cudaFuncAttributeMaxDynamicSharedMemorySize, GSMEM_BYTES);
    cudaFuncSetAttribute(mma_gemm<false, false>, cudaFuncAttributeMaxDynamicSharedMemorySize, GSMEM_BYTES);
    cudaFuncSetAttribute(mma_gemm<true, false>,  cudaFuncAttributeMaxDynamicSharedMemorySize, GSMEM_BYTES);

    const int GX = (N_ + 127) / 128;  // 391

    pack_x2_kernel<<<4096, 256>>>(node_feat, memory);
    pack_b_kernel<<<6, 256>>>(wk_b, wv_b, wq_b, wq_w, te_phi);
    pack_wall_base_kernel<<<2304, 256>>>(wk_w, wv_w, wq_w);
    pack_wall_fused_kernel<<<640, 256>>>(wk_w, wq_w);
    pack_bias_split_kernel<<<4, 256>>>();
    conv_kqp_kernel<<<1664, 256>>>();
    conv_v_kernel<<<512, 256>>>();
    conv_dup_kernel<<<512, 256>>>((const float*)in_w, 256, 256, pWin2, 512);
    conv_dup_kernel<<<128, 256>>>((const float*)out_w, 64, 256, pWout2, 512);
    conv_dup_kernel<<<384, 256>>>(pWev, 2 * 256, 80, pWev2, 192);

    // CSR build (topology is layer-independent)
    csr_zero_kernel<<<(N_ + 255) / 256, 256>>>();
    csr_count_kernel<<<(E_ + 255) / 256, 256>>>(dst);
    csr_scan_kernel<<<1, 1024>>>();
    csr_fill_kernel<<<(E_ + 255) / 256, 256>>>(dst);

    // h = X @ in_w^T + in_b (also emits h2 split)
    mma_gemm<false, true><<<dim3(GX, 2), 256, GSMEM_BYTES>>>(
        pX2, 512, 512, pWin2, 512, 256, in_b, ph, 256, N_, 256, ph2);

    for (int l = 0; l < 2; l++) {
        // [K'|Q'|P] = h @ Wkqp^T + [bk|bq_eff|cb]   (2-term split, K=512)
        mma_gemm<false, false><<<dim3(GX, 7), 256, GSMEM_BYTES>>>(
            ph2, 512, 512, pWkqp2 + (size_t)l * 832 * 512, 512, 832,
            pBiasKQP + l * 832, phkvqp, 1152, N_, 832, nullptr);
        // V' = h_hi @ Wv^T + bv   (hi-only, K=256)
        mma_gemm<false, false><<<dim3(GX, 2), 256, GSMEM_BYTES>>>(
            ph2, 512, 256, pWv2h + (size_t)l * 256 * 256, 256, 256,
            pBiasV + l * 256, phkvqp + 832, 1152, N_, 256, nullptr);
        node_attn_kernel<<<6250, 256>>>(src, dst, edge_feat, edge_times, te_w, te_phi, l);
        // agg2 = aggm @ We_v^T
        mma_gemm<false, false><<<dim3(GX, 2), 256, GSMEM_BYTES>>>(
            pAggm2, 192, 192, pWev2 + (size_t)l * 256 * 192, 192, 256,
            nullptr, pAgg2, 256, N_, 256, nullptr);
        node_update_kernel<<<6250, 256>>>(attn_ln_w + l * 256, attn_ln_b + l * 256,
                                          ln_w + l * 256, ln_b + l * 256);
    }

    // out = gelu(h @ out_w^T + out_b)
    mma_gemm<true, false><<<dim3(GX, 1), 256, GSMEM_BYTES>>>(
        ph2, 512, 512, pWout2, 512, 64, out_b, out, 64, N_, 64, nullptr);
}